// round 1
// baseline (speedup 1.0000x reference)
#include <cuda_runtime.h>
#include <cuda_bf16.h>
#include <math.h>

// ---------------- problem constants ----------------
#define NNODES   50000
#define NEDGES   800000
#define NH       256
#define EH       64
#define NSTEPS   10
#define EPSV     0.01f

// ---------------- scratch (device globals, no allocation) ----------------
__device__ float  g_hs[NNODES * 32];
__device__ float  g_hd[NNODES * 32];
__device__ float2 g_coef[NEDGES];
__device__ float4 g_coords[NNODES];
__device__ float  g_aggr[NNODES * 4];

// ============================================================
// Kernel 1: node GEMM  P = node_emb @ [Wt1 | Ws | Wd]  (M x 256 x 192)
// fused epilogue: hs/hd stores + torsion head (leaky -> @Wt2 -> rho/phi/theta)
// ============================================================
#define BM 64
#define BN 192
#define BK 16

__global__ __launch_bounds__(256, 2)
void node_gemm_kernel(const float* __restrict__ A,      // node_emb [M,256]
                      const float* __restrict__ Wt1,    // [256,128]
                      const float* __restrict__ bt1,    // [128]
                      const float* __restrict__ Wt2,    // [128,3]
                      const float* __restrict__ bt2,    // [3]
                      const float* __restrict__ Wr1,    // [576,32]
                      float* __restrict__ out_torsion,  // d_out + 3*M
                      int M)
{
    // pool overlays: during mainloop As[64][16] + Bs[16][192]; during epilogue Hs[64][129]
    __shared__ float pool[64 * 129];
    float* As = pool;              // 64*16 = 1024
    float* Bs = pool + 64 * 16;    // 16*192 = 3072
    __shared__ float sWt2[128 * 3];
    __shared__ float sbt1[128];
    __shared__ float sbt2[3];

    const int tid = threadIdx.x;
    const int cx  = tid & 31;     // col lane
    const int ry  = tid >> 5;     // row group 0..7
    const int m0  = blockIdx.x * BM;

    if (tid < 128) sbt1[tid] = bt1[tid];
    if (tid < 128) {
        sWt2[tid * 3 + 0] = Wt2[tid * 3 + 0];
        sWt2[tid * 3 + 1] = Wt2[tid * 3 + 1];
        sWt2[tid * 3 + 2] = Wt2[tid * 3 + 2];
    }
    if (tid < 3) sbt2[tid] = bt2[tid];

    float c[8][6];
#pragma unroll
    for (int i = 0; i < 8; i++)
#pragma unroll
        for (int j = 0; j < 6; j++) c[i][j] = 0.f;

    const int r_load = tid >> 2;        // 0..63
    const int kq     = tid & 3;         // 0..3 (float4 chunk)

    for (int kb = 0; kb < NH; kb += BK) {
        // --- load A tile (64 x 16) as float4, store As[r][k] ---
        {
            float4 v = make_float4(0.f, 0.f, 0.f, 0.f);
            int m = m0 + r_load;
            if (m < M) v = *reinterpret_cast<const float4*>(A + (size_t)m * NH + kb + kq * 4);
            As[r_load * 16 + kq * 4 + 0] = v.x;
            As[r_load * 16 + kq * 4 + 1] = v.y;
            As[r_load * 16 + kq * 4 + 2] = v.z;
            As[r_load * 16 + kq * 4 + 3] = v.w;
        }
        // --- load B tile (16 x 192) concatenated from Wt1 / Wr1 slices ---
#pragma unroll
        for (int q = 0; q < 12; q++) {
            int l = q * 256 + tid;        // 0..3071
            int k = l / BN;
            int n = l - k * BN;
            int kk = kb + k;
            float v;
            if (n < 128)      v = Wt1[kk * 128 + n];
            else if (n < 160) v = Wr1[(64 + kk) * 32 + (n - 128)];
            else              v = Wr1[(320 + kk) * 32 + (n - 160)];
            Bs[k * BN + n] = v;
        }
        __syncthreads();
#pragma unroll
        for (int k = 0; k < BK; k++) {
            float a[8], b[6];
#pragma unroll
            for (int i = 0; i < 8; i++) a[i] = As[(ry + 8 * i) * 16 + k];
#pragma unroll
            for (int j = 0; j < 6; j++) b[j] = Bs[k * BN + cx + 32 * j];
#pragma unroll
            for (int i = 0; i < 8; i++)
#pragma unroll
                for (int j = 0; j < 6; j++) c[i][j] = fmaf(a[i], b[j], c[i][j]);
        }
        __syncthreads();
    }

    // --- epilogue 1: hs (cols 128..159 -> j=4), hd (160..191 -> j=5) ---
#pragma unroll
    for (int i = 0; i < 8; i++) {
        int m = m0 + ry + 8 * i;
        if (m < M) {
            g_hs[m * 32 + cx] = c[i][4];
            g_hd[m * 32 + cx] = c[i][5];
        }
    }

    // --- epilogue 2: leaky(h1 + bt1) into Hs overlay ---
    float* Hs = pool;   // [64][129]
#pragma unroll
    for (int i = 0; i < 8; i++) {
#pragma unroll
        for (int j = 0; j < 4; j++) {
            int n = cx + 32 * j;
            float v = c[i][j] + sbt1[n];
            v = (v >= 0.f) ? v : 0.01f * v;
            Hs[(ry + 8 * i) * 129 + n] = v;
        }
    }
    __syncthreads();

    // --- epilogue 3: torsion head, one thread per row ---
    if (tid < 64) {
        int m = m0 + tid;
        if (m < M) {
            float t0 = sbt2[0], t1 = sbt2[1], t2 = sbt2[2];
            const float* hr = Hs + tid * 129;
#pragma unroll 8
            for (int n = 0; n < 128; n++) {
                float h = hr[n];
                t0 = fmaf(h, sWt2[n * 3 + 0], t0);
                t1 = fmaf(h, sWt2[n * 3 + 1], t1);
                t2 = fmaf(h, sWt2[n * 3 + 2], t2);
            }
            float rho = sqrtf(t0 * t0 + t1 * t1 + t2 * t2);
            float inv = 1.0f / rho;
            float n0 = t0 * inv, n1 = t1 * inv, n2 = t2 * inv;
            float theta = (fabsf(n0) > fabsf(n1)) ? atan2f(n1, n0)
                                                  : (1.5707963267948966f - atan2f(n0, n1));
            float cz = fminf(fmaxf(n2, -1.0f + EPSV), 1.0f - EPSV);
            float phi = acosf(cz);
            out_torsion[(size_t)m * 3 + 0] = rho;
            out_torsion[(size_t)m * 3 + 1] = phi;
            out_torsion[(size_t)m * 3 + 2] = theta;
        }
    }
}

// ============================================================
// Kernel 2: edge MLP -> per-edge (edge_len, 2*step_size)
// warp per edge; lane j owns weight column j of We (64 regs)
// ============================================================
__global__ __launch_bounds__(256)
void edge_mlp_kernel(const float* __restrict__ edge_emb,  // [E,64]
                     const float* __restrict__ Wr1,       // [576,32]
                     const float* __restrict__ br1,       // [32]
                     const float* __restrict__ Wr2,       // [32,2]
                     const float* __restrict__ br2,       // [2]
                     const int*   __restrict__ eidx,      // [2,E]
                     int E)
{
    const int lane = threadIdx.x & 31;
    const int wid  = (blockIdx.x * blockDim.x + threadIdx.x) >> 5;
    const int nw   = (gridDim.x * blockDim.x) >> 5;

    float wc[64];
#pragma unroll
    for (int k = 0; k < 64; k++) wc[k] = Wr1[k * 32 + lane];   // We column
    const float b1  = br1[lane];
    const float w2a = Wr2[lane * 2 + 0];
    const float w2b = Wr2[lane * 2 + 1];
    const float b20 = br2[0], b21 = br2[1];

    for (int e = wid; e < E; e += nw) {
        int src = eidx[e];
        int dst = eidx[E + e];
        float e0 = edge_emb[(size_t)e * EH + lane];
        float e1 = edge_emb[(size_t)e * EH + 32 + lane];
        float h  = g_hs[src * 32 + lane] + g_hd[dst * 32 + lane] + b1;
#pragma unroll
        for (int k = 0; k < 32; k++) h = fmaf(__shfl_sync(0xffffffffu, e0, k), wc[k], h);
#pragma unroll
        for (int k = 0; k < 32; k++) h = fmaf(__shfl_sync(0xffffffffu, e1, k), wc[32 + k], h);
        h = (h >= 0.f) ? h : 0.01f * h;
        float v0 = h * w2a;
        float v1 = h * w2b;
#pragma unroll
        for (int o = 16; o; o >>= 1) {
            v0 += __shfl_xor_sync(0xffffffffu, v0, o);
            v1 += __shfl_xor_sync(0xffffffffu, v1, o);
        }
        if (lane == 0) {
            float x = v0 + b20 + 1.0f;                                  // softplus
            float elen = fmaxf(x, 0.f) + log1pf(expf(-fabsf(x)));
            float y = v1 + b21 - 2.0f;                                  // sigmoid
            float sg = 1.0f / (1.0f + expf(-y));
            g_coef[e] = make_float2(elen, 2.0f * sg);
        }
    }
}

// ============================================================
// Refiner kernels
// ============================================================
__global__ void init_kernel(const float* __restrict__ cart, int N)
{
    int n = blockIdx.x * blockDim.x + threadIdx.x;
    if (n >= N) return;
    g_coords[n] = make_float4(cart[n * 3 + 0], cart[n * 3 + 1], cart[n * 3 + 2], 0.f);
    g_aggr[n * 4 + 0] = 0.f;
    g_aggr[n * 4 + 1] = 0.f;
    g_aggr[n * 4 + 2] = 0.f;
}

__global__ __launch_bounds__(256)
void scatter_kernel(const int* __restrict__ eidx, int E)
{
    int e = blockIdx.x * blockDim.x + threadIdx.x;
    if (e >= E) return;
    int s = eidx[e];
    int d = eidx[E + e];
    float4 cs = g_coords[s];
    float4 cd = g_coords[d];
    float dx = cd.x - cs.x, dy = cd.y - cs.y, dz = cd.z - cs.z;
    float dist = sqrtf(dx * dx + dy * dy + dz * dz);
    float2 cf = g_coef[e];
    float f = cf.y * (cf.x - dist) / (dist + EPSV);
    atomicAdd(&g_aggr[d * 4 + 0], f * dx);
    atomicAdd(&g_aggr[d * 4 + 1], f * dy);
    atomicAdd(&g_aggr[d * 4 + 2], f * dz);
}

__global__ void update_kernel(float* __restrict__ out_coords, int last, int N)
{
    int n = blockIdx.x * blockDim.x + threadIdx.x;
    if (n >= N) return;
    float ax = g_aggr[n * 4 + 0];
    float ay = g_aggr[n * 4 + 1];
    float az = g_aggr[n * 4 + 2];
    float an = sqrtf(ax * ax + ay * ay + az * az) + EPSV;
    float sc = fminf(an, 0.5f) / an;
    float4 c = g_coords[n];
    c.x += ax * sc; c.y += ay * sc; c.z += az * sc;
    g_coords[n] = c;
    g_aggr[n * 4 + 0] = 0.f;
    g_aggr[n * 4 + 1] = 0.f;
    g_aggr[n * 4 + 2] = 0.f;
    if (last) {
        out_coords[n * 3 + 0] = c.x;
        out_coords[n * 3 + 1] = c.y;
        out_coords[n * 3 + 2] = c.z;
    }
}

// ============================================================
// launch
// ============================================================
extern "C" void kernel_launch(void* const* d_in, const int* in_sizes, int n_in,
                              void* d_out, int out_size)
{
    const float* node_emb  = (const float*)d_in[0];
    const float* edge_emb  = (const float*)d_in[1];
    const float* cart_init = (const float*)d_in[2];
    const float* Wt1       = (const float*)d_in[3];
    const float* bt1       = (const float*)d_in[4];
    const float* Wt2       = (const float*)d_in[5];
    const float* bt2       = (const float*)d_in[6];
    const float* Wr1       = (const float*)d_in[7];
    const float* br1       = (const float*)d_in[8];
    const float* Wr2       = (const float*)d_in[9];
    const float* br2       = (const float*)d_in[10];
    const int*   eidx      = (const int*)d_in[11];

    const int M = in_sizes[0] / NH;        // 50000
    const int E = in_sizes[1] / EH;        // 800000

    float* out = (float*)d_out;
    float* out_coords  = out;              // first M*3
    float* out_torsion = out + (size_t)M * 3;

    // 1. node GEMM + torsion head + hs/hd
    node_gemm_kernel<<<(M + BM - 1) / BM, 256>>>(node_emb, Wt1, bt1, Wt2, bt2, Wr1,
                                                 out_torsion, M);
    // 2. edge MLP -> coefficients
    edge_mlp_kernel<<<1184, 256>>>(edge_emb, Wr1, br1, Wr2, br2, eidx, E);
    // 3. refiner
    init_kernel<<<(M + 255) / 256, 256>>>(cart_init, M);
    for (int s = 0; s < NSTEPS; s++) {
        scatter_kernel<<<(E + 255) / 256, 256>>>(eidx, E);
        update_kernel<<<(M + 255) / 256, 256>>>(out_coords, (s == NSTEPS - 1) ? 1 : 0, M);
    }
}

// round 2
// speedup vs baseline: 1.4768x; 1.4768x over previous
#include <cuda_runtime.h>
#include <cuda_bf16.h>
#include <math.h>

// ---------------- problem constants ----------------
#define NNODES   50000
#define NEDGES   800000
#define NH       256
#define EH       64
#define NSTEPS   10
#define EPSV     0.01f
#define NB_SCAN  196          // ceil(50000/256)

// ---------------- scratch (device globals, no allocation) ----------------
__device__ float  g_hs[NNODES * 32];
__device__ float  g_hd[NNODES * 32];
__device__ int    g_deg[NNODES];
__device__ int    g_ptr[NNODES];
__device__ int    g_cursor[NNODES];
__device__ int    g_bsum[256];
__device__ int    g_boff[256];
__device__ int    g_pos[NEDGES];
__device__ float4 g_ecsr[NEDGES];     // .x = elen, .y = 2*step, .z = src (bits)
__device__ float4 g_cA[NNODES];
__device__ float4 g_cB[NNODES];

// ============================================================
// Kernel 1: node GEMM  P = node_emb @ [Wt1 | Ws | Wd]  (M x 256 x 192)
// epilogue: hs/hd stores + torsion head via per-thread partials + warp reduce
// ============================================================
#define BM 64
#define BN 192
#define BK 16

__global__ __launch_bounds__(256, 3)
void node_gemm_kernel(const float* __restrict__ A,      // node_emb [M,256]
                      const float* __restrict__ Wt1,    // [256,128]
                      const float* __restrict__ bt1,    // [128]
                      const float* __restrict__ Wt2,    // [128,3]
                      const float* __restrict__ bt2,    // [3]
                      const float* __restrict__ Wr1,    // [576,32]
                      float* __restrict__ out_torsion,
                      int M)
{
    __shared__ float As[BM * BK];       // 1024
    __shared__ float Bs[BK * BN];       // 3072
    __shared__ float sWt2[128 * 3];
    __shared__ float sbt1[128];
    __shared__ float sbt2[3];

    const int tid = threadIdx.x;
    const int cx  = tid & 31;
    const int ry  = tid >> 5;
    const int m0  = blockIdx.x * BM;

    if (tid < 128) {
        sbt1[tid] = bt1[tid];
        sWt2[tid * 3 + 0] = Wt2[tid * 3 + 0];
        sWt2[tid * 3 + 1] = Wt2[tid * 3 + 1];
        sWt2[tid * 3 + 2] = Wt2[tid * 3 + 2];
    }
    if (tid < 3) sbt2[tid] = bt2[tid];

    float c[8][6];
#pragma unroll
    for (int i = 0; i < 8; i++)
#pragma unroll
        for (int j = 0; j < 6; j++) c[i][j] = 0.f;

    const int r_load = tid >> 2;
    const int kq     = tid & 3;

    for (int kb = 0; kb < NH; kb += BK) {
        // A tile (64 x 16)
        {
            float4 v = make_float4(0.f, 0.f, 0.f, 0.f);
            int m = m0 + r_load;
            if (m < M) v = *reinterpret_cast<const float4*>(A + (size_t)m * NH + kb + kq * 4);
            As[r_load * 16 + kq * 4 + 0] = v.x;
            As[r_load * 16 + kq * 4 + 1] = v.y;
            As[r_load * 16 + kq * 4 + 2] = v.z;
            As[r_load * 16 + kq * 4 + 3] = v.w;
        }
        // B tile (16 x 192) : [Wt1 cols 0..127 | Ws cols | Wd cols], float4 loads
#pragma unroll
        for (int q = 0; q < 2; q++) {
            int idx = q * 256 + tid;
            int row = idx >> 5, c4 = idx & 31;
            float4 v = *reinterpret_cast<const float4*>(Wt1 + (size_t)(kb + row) * 128 + c4 * 4);
            *reinterpret_cast<float4*>(&Bs[row * BN + c4 * 4]) = v;
        }
        if (tid < 128) {
            int row = tid >> 3, c4 = tid & 7;
            float4 v = *reinterpret_cast<const float4*>(Wr1 + (size_t)(64 + kb + row) * 32 + c4 * 4);
            *reinterpret_cast<float4*>(&Bs[row * BN + 128 + c4 * 4]) = v;
        } else {
            int t = tid - 128;
            int row = t >> 3, c4 = t & 7;
            float4 v = *reinterpret_cast<const float4*>(Wr1 + (size_t)(320 + kb + row) * 32 + c4 * 4);
            *reinterpret_cast<float4*>(&Bs[row * BN + 160 + c4 * 4]) = v;
        }
        __syncthreads();
#pragma unroll
        for (int k = 0; k < BK; k++) {
            float a[8], b[6];
#pragma unroll
            for (int i = 0; i < 8; i++) a[i] = As[(ry + 8 * i) * 16 + k];
#pragma unroll
            for (int j = 0; j < 6; j++) b[j] = Bs[k * BN + cx + 32 * j];
#pragma unroll
            for (int i = 0; i < 8; i++)
#pragma unroll
                for (int j = 0; j < 6; j++) c[i][j] = fmaf(a[i], b[j], c[i][j]);
        }
        __syncthreads();
    }

    // hs / hd
#pragma unroll
    for (int i = 0; i < 8; i++) {
        int m = m0 + ry + 8 * i;
        if (m < M) {
            g_hs[m * 32 + cx] = c[i][4];
            g_hd[m * 32 + cx] = c[i][5];
        }
    }

    // torsion head: per-thread partial over its 4 hidden cols, warp reduce
#pragma unroll
    for (int i = 0; i < 8; i++) {
        float p0 = 0.f, p1 = 0.f, p2 = 0.f;
#pragma unroll
        for (int j = 0; j < 4; j++) {
            int n = cx + 32 * j;
            float v = c[i][j] + sbt1[n];
            v = (v >= 0.f) ? v : 0.01f * v;
            p0 = fmaf(v, sWt2[n * 3 + 0], p0);
            p1 = fmaf(v, sWt2[n * 3 + 1], p1);
            p2 = fmaf(v, sWt2[n * 3 + 2], p2);
        }
#pragma unroll
        for (int o = 16; o; o >>= 1) {
            p0 += __shfl_xor_sync(0xffffffffu, p0, o);
            p1 += __shfl_xor_sync(0xffffffffu, p1, o);
            p2 += __shfl_xor_sync(0xffffffffu, p2, o);
        }
        if (cx == 0) {
            int m = m0 + ry + 8 * i;
            if (m < M) {
                float t0 = p0 + sbt2[0], t1 = p1 + sbt2[1], t2 = p2 + sbt2[2];
                float rho = sqrtf(t0 * t0 + t1 * t1 + t2 * t2);
                float inv = 1.0f / rho;
                float n0 = t0 * inv, n1 = t1 * inv, n2 = t2 * inv;
                float theta = (fabsf(n0) > fabsf(n1)) ? atan2f(n1, n0)
                                                      : (1.5707963267948966f - atan2f(n0, n1));
                float cz = fminf(fmaxf(n2, -1.0f + EPSV), 1.0f - EPSV);
                float phi = acosf(cz);
                out_torsion[(size_t)m * 3 + 0] = rho;
                out_torsion[(size_t)m * 3 + 1] = phi;
                out_torsion[(size_t)m * 3 + 2] = theta;
            }
        }
    }
}

// ============================================================
// CSR build
// ============================================================
__global__ void init_kernel(const float* __restrict__ cart, int N)
{
    int n = blockIdx.x * blockDim.x + threadIdx.x;
    if (n >= N) return;
    g_cA[n] = make_float4(cart[n * 3 + 0], cart[n * 3 + 1], cart[n * 3 + 2], 0.f);
    g_deg[n] = 0;
}

__global__ void count_kernel(const int* __restrict__ eidx, int E)
{
    int e = blockIdx.x * blockDim.x + threadIdx.x;
    if (e >= E) return;
    atomicAdd(&g_deg[eidx[E + e]], 1);
}

__global__ void scan1_kernel(int N)
{
    __shared__ int s[256];
    int t = threadIdx.x;
    int n = blockIdx.x * 256 + t;
    int v = (n < N) ? g_deg[n] : 0;
    s[t] = v;
    __syncthreads();
#pragma unroll
    for (int o = 1; o < 256; o <<= 1) {
        int x = (t >= o) ? s[t - o] : 0;
        __syncthreads();
        s[t] += x;
        __syncthreads();
    }
    if (n < N) g_ptr[n] = s[t] - v;          // local exclusive
    if (t == 255) g_bsum[blockIdx.x] = s[255];
}

__global__ void scan2_kernel(int nb)
{
    __shared__ int s[256];
    int t = threadIdx.x;
    int v = (t < nb) ? g_bsum[t] : 0;
    s[t] = v;
    __syncthreads();
#pragma unroll
    for (int o = 1; o < 256; o <<= 1) {
        int x = (t >= o) ? s[t - o] : 0;
        __syncthreads();
        s[t] += x;
        __syncthreads();
    }
    if (t < nb) g_boff[t] = s[t] - v;        // exclusive
}

__global__ void scan3_kernel(int N)
{
    int n = blockIdx.x * blockDim.x + threadIdx.x;
    if (n >= N) return;
    int p = g_ptr[n] + g_boff[blockIdx.x * 256 / 256 == 0 ? blockIdx.x : blockIdx.x];
    p = g_ptr[n] + g_boff[n >> 8];
    g_ptr[n] = p;
    g_cursor[n] = p;
}

__global__ void fill_kernel(const int* __restrict__ eidx, int E)
{
    int e = blockIdx.x * blockDim.x + threadIdx.x;
    if (e >= E) return;
    int s = eidx[e];
    int d = eidx[E + e];
    int slot = atomicAdd(&g_cursor[d], 1);
    reinterpret_cast<float*>(g_ecsr)[slot * 4 + 2] = __int_as_float(s);
    g_pos[e] = slot;
}

// ============================================================
// Kernel 2: edge MLP, register-tiled GEMM (256 edges/block, 128 threads,
// thread tile = 8 edges x 8 dims). Writes coef into CSR slots.
// ============================================================
#define EMLP_SMEM_FLOATS (256 * 68 + 64 * 32 + 64 + 34)

__global__ __launch_bounds__(128, 2)
void edge_mlp_kernel(const float* __restrict__ edge_emb,  // [E,64]
                     const float* __restrict__ Wr1,       // [576,32]
                     const float* __restrict__ br1,       // [32]
                     const float* __restrict__ Wr2,       // [32,2]
                     const float* __restrict__ br2,       // [2]
                     const int*   __restrict__ eidx,      // [2,E]
                     int E)
{
    extern __shared__ float sm[];
    float* Es   = sm;                      // 256 * 68 (padded rows)
    float* sWe  = sm + 256 * 68;           // 64 * 32
    float* sWr2 = sWe + 64 * 32;           // 64
    float* sb   = sWr2 + 64;               // 32 br1 + 2 br2

    const int tid = threadIdx.x;
    const int eb  = blockIdx.x * 256;

    for (int i = tid; i < 2048; i += 128) sWe[i] = Wr1[i];   // We = Wr1[0:64]
    if (tid < 64) sWr2[tid] = Wr2[tid];
    if (tid < 32) sb[tid] = br1[tid];
    if (tid < 2)  sb[32 + tid] = br2[tid];

    // stage 256 edge rows (coalesced float4)
#pragma unroll
    for (int i = 0; i < 32; i++) {
        int gid = tid + 128 * i;
        int e = gid >> 4, q = gid & 15;
        float4 v = *reinterpret_cast<const float4*>(edge_emb + (size_t)(eb + e) * 64 + q * 4);
        *reinterpret_cast<float4*>(Es + e * 68 + q * 4) = v;
    }
    __syncthreads();

    const int eg = tid >> 2;     // 0..31 : edge group
    const int dg = tid & 3;      // 0..3  : dim group (8 dims each)

    float acc[8][8];
#pragma unroll
    for (int i = 0; i < 8; i++)
#pragma unroll
        for (int j = 0; j < 8; j++) acc[i][j] = 0.f;

    int rowbase[8];
#pragma unroll
    for (int i = 0; i < 8; i++) rowbase[i] = (eg + 32 * i) * 68;

#pragma unroll 8
    for (int k = 0; k < 64; k++) {
        float4 b0 = *reinterpret_cast<float4*>(sWe + k * 32 + dg * 8);
        float4 b1 = *reinterpret_cast<float4*>(sWe + k * 32 + dg * 8 + 4);
        float a[8];
#pragma unroll
        for (int i = 0; i < 8; i++) a[i] = Es[rowbase[i] + k];
#pragma unroll
        for (int i = 0; i < 8; i++) {
            acc[i][0] = fmaf(a[i], b0.x, acc[i][0]);
            acc[i][1] = fmaf(a[i], b0.y, acc[i][1]);
            acc[i][2] = fmaf(a[i], b0.z, acc[i][2]);
            acc[i][3] = fmaf(a[i], b0.w, acc[i][3]);
            acc[i][4] = fmaf(a[i], b1.x, acc[i][4]);
            acc[i][5] = fmaf(a[i], b1.y, acc[i][5]);
            acc[i][6] = fmaf(a[i], b1.z, acc[i][6]);
            acc[i][7] = fmaf(a[i], b1.w, acc[i][7]);
        }
    }

    // epilogue
#pragma unroll
    for (int i = 0; i < 8; i++) {
        int ge = eb + eg + 32 * i;
        int s = eidx[ge];
        int d = eidx[E + ge];
        float4 hs0 = *reinterpret_cast<const float4*>(g_hs + s * 32 + dg * 8);
        float4 hs1 = *reinterpret_cast<const float4*>(g_hs + s * 32 + dg * 8 + 4);
        float4 hd0 = *reinterpret_cast<const float4*>(g_hd + d * 32 + dg * 8);
        float4 hd1 = *reinterpret_cast<const float4*>(g_hd + d * 32 + dg * 8 + 4);
        float add[8] = {hs0.x + hd0.x, hs0.y + hd0.y, hs0.z + hd0.z, hs0.w + hd0.w,
                        hs1.x + hd1.x, hs1.y + hd1.y, hs1.z + hd1.z, hs1.w + hd1.w};
        float v0 = 0.f, v1 = 0.f;
#pragma unroll
        for (int j = 0; j < 8; j++) {
            float h = acc[i][j] + add[j] + sb[dg * 8 + j];
            h = (h >= 0.f) ? h : 0.01f * h;
            v0 = fmaf(h, sWr2[(dg * 8 + j) * 2 + 0], v0);
            v1 = fmaf(h, sWr2[(dg * 8 + j) * 2 + 1], v1);
        }
        v0 += __shfl_xor_sync(0xffffffffu, v0, 1);
        v0 += __shfl_xor_sync(0xffffffffu, v0, 2);
        v1 += __shfl_xor_sync(0xffffffffu, v1, 1);
        v1 += __shfl_xor_sync(0xffffffffu, v1, 2);
        if (dg == 0) {
            float x = v0 + sb[32] + 1.0f;
            float elen = fmaxf(x, 0.f) + log1pf(expf(-fabsf(x)));
            float y = v1 + sb[33] - 2.0f;
            float sg = 1.0f / (1.0f + expf(-y));
            int slot = g_pos[ge];
            float* dst = reinterpret_cast<float*>(g_ecsr) + (size_t)slot * 4;
            dst[0] = elen;
            dst[1] = 2.0f * sg;
        }
    }
}

// ============================================================
// Refiner: one gather kernel per step (ping-pong buffers, no atomics)
// ============================================================
__global__ __launch_bounds__(256)
void refine_step_kernel(const float4* __restrict__ cin, float4* __restrict__ cout,
                        float* __restrict__ out_coords, int last, int N)
{
    int n = blockIdx.x * blockDim.x + threadIdx.x;
    if (n >= N) return;
    float4 c = cin[n];
    int p = g_ptr[n];
    int d = g_deg[n];
    float ax = 0.f, ay = 0.f, az = 0.f;
#pragma unroll 4
    for (int i = 0; i < d; i++) {
        float4 er = g_ecsr[p + i];
        int s = __float_as_int(er.z);
        float4 cs = cin[s];
        float dx = c.x - cs.x, dy = c.y - cs.y, dz = c.z - cs.z;
        float dist = sqrtf(dx * dx + dy * dy + dz * dz);
        float f = er.y * (er.x - dist) / (dist + EPSV);
        ax = fmaf(f, dx, ax);
        ay = fmaf(f, dy, ay);
        az = fmaf(f, dz, az);
    }
    float an = sqrtf(ax * ax + ay * ay + az * az) + EPSV;
    float sc = fminf(an, 0.5f) / an;
    c.x += ax * sc; c.y += ay * sc; c.z += az * sc;
    cout[n] = c;
    if (last) {
        out_coords[n * 3 + 0] = c.x;
        out_coords[n * 3 + 1] = c.y;
        out_coords[n * 3 + 2] = c.z;
    }
}

// ============================================================
// launch
// ============================================================
extern "C" void kernel_launch(void* const* d_in, const int* in_sizes, int n_in,
                              void* d_out, int out_size)
{
    const float* node_emb  = (const float*)d_in[0];
    const float* edge_emb  = (const float*)d_in[1];
    const float* cart_init = (const float*)d_in[2];
    const float* Wt1       = (const float*)d_in[3];
    const float* bt1       = (const float*)d_in[4];
    const float* Wt2       = (const float*)d_in[5];
    const float* bt2       = (const float*)d_in[6];
    const float* Wr1       = (const float*)d_in[7];
    const float* br1       = (const float*)d_in[8];
    const float* Wr2       = (const float*)d_in[9];
    const float* br2       = (const float*)d_in[10];
    const int*   eidx      = (const int*)d_in[11];

    const int M = in_sizes[0] / NH;        // 50000
    const int E = in_sizes[1] / EH;        // 800000

    float* out = (float*)d_out;
    float* out_coords  = out;
    float* out_torsion = out + (size_t)M * 3;

    static bool attr_set = false;
    if (!attr_set) {
        cudaFuncSetAttribute(edge_mlp_kernel, cudaFuncAttributeMaxDynamicSharedMemorySize,
                             EMLP_SMEM_FLOATS * 4);
        attr_set = true;
    }

    const int nb_nodes = (M + 255) / 256;
    const int nb_edges = (E + 255) / 256;

    // 1. node GEMM + torsion head + hs/hd
    node_gemm_kernel<<<(M + BM - 1) / BM, 256>>>(node_emb, Wt1, bt1, Wt2, bt2, Wr1,
                                                 out_torsion, M);
    // 2. CSR build
    init_kernel<<<nb_nodes, 256>>>(cart_init, M);
    count_kernel<<<nb_edges, 256>>>(eidx, E);
    scan1_kernel<<<nb_nodes, 256>>>(M);
    scan2_kernel<<<1, 256>>>(nb_nodes);
    scan3_kernel<<<nb_nodes, 256>>>(M);
    fill_kernel<<<nb_edges, 256>>>(eidx, E);
    // 3. edge MLP -> coefficients into CSR slots
    edge_mlp_kernel<<<nb_edges, 128, EMLP_SMEM_FLOATS * 4>>>(edge_emb, Wr1, br1, Wr2, br2,
                                                             eidx, E);
    // 4. refiner (ping-pong)
    float4* bufs[2];
    cudaGetSymbolAddress((void**)&bufs[0], g_cA);
    cudaGetSymbolAddress((void**)&bufs[1], g_cB);
    for (int s = 0; s < NSTEPS; s++) {
        refine_step_kernel<<<nb_nodes, 256>>>(bufs[s & 1], bufs[(s + 1) & 1],
                                              out_coords, (s == NSTEPS - 1) ? 1 : 0, M);
    }
}

// round 4
// speedup vs baseline: 1.6732x; 1.1330x over previous
#include <cuda_runtime.h>
#include <cuda_bf16.h>
#include <math.h>

// ---------------- problem constants ----------------
#define NNODES   50000
#define NEDGES   800000
#define NH       256
#define EH       64
#define NSTEPS   10
#define EPSV     0.01f

// ---------------- scratch (device globals, no allocation) ----------------
__device__ float  g_hs[NNODES * 32];
__device__ float  g_hd[NNODES * 32];
__device__ int    g_deg[NNODES];
__device__ int    g_ptr[NNODES];
__device__ int    g_cursor[NNODES];
__device__ int    g_bsum[256];
__device__ int    g_boff[256];
__device__ int    g_pos[NEDGES];
__device__ float4 g_ecsr[NEDGES];     // .x = elen, .y = 2*step, .z = src (bits)
__device__ float4 g_cA[NNODES];
__device__ float4 g_cB[NNODES];

// ============================================================
// tf32 mma helpers
// ============================================================
__device__ __forceinline__ unsigned f2tf32(float f)
{
    unsigned u;
    asm("cvt.rna.tf32.f32 %0, %1;" : "=r"(u) : "f"(f));
    return u;
}

__device__ __forceinline__ void split_tf32(float v, unsigned& hi, unsigned& lo)
{
    hi = f2tf32(v);
    lo = f2tf32(v - __uint_as_float(hi));
}

__device__ __forceinline__ void mma_tf32(float4& d,
                                         unsigned a0, unsigned a1, unsigned a2, unsigned a3,
                                         unsigned b0, unsigned b1)
{
    asm volatile("mma.sync.aligned.m16n8k8.row.col.f32.tf32.tf32.f32 "
                 "{%0,%1,%2,%3}, {%4,%5,%6,%7}, {%8,%9}, {%0,%1,%2,%3};"
                 : "+f"(d.x), "+f"(d.y), "+f"(d.z), "+f"(d.w)
                 : "r"(a0), "r"(a1), "r"(a2), "r"(a3), "r"(b0), "r"(b1));
}

// ============================================================
// Kernel 1: node GEMM via tensor cores (3xTF32 = fp32-accurate)
// C = node_emb @ [Wt1 | Ws | Wd]   (M x 256 x 192)
// CTA tile 64x192x16, 8 warps (2x4), warp tile 32x48 (m16n8k8 frags)
// acc += Ahi*Bhi + Ahi*Blo + Alo*Bhi
// epilogue: hs/hd float2 stores + torsion head (leaky -> @Wt2 -> rho/phi/theta)
// ============================================================
#define TBM 64
#define TBN 192
#define TBK 16
#define ASTR 20      // bank = (20m+k)%32 over fragment lanes -> conflict-free
#define BSTR 200     // bank = (8k+n)%32 -> conflict-free

__global__ __launch_bounds__(256)
void node_gemm_tc(const float* __restrict__ A,      // node_emb [M,256]
                  const float* __restrict__ Wt1,    // [256,128]
                  const float* __restrict__ bt1,    // [128]
                  const float* __restrict__ Wt2,    // [128,3]
                  const float* __restrict__ bt2,    // [3]
                  const float* __restrict__ Wr1,    // [576,32]
                  float* __restrict__ out_torsion,
                  int M)
{
    __shared__ unsigned AsH[TBM * ASTR];   // 1280
    __shared__ unsigned AsL[TBM * ASTR];
    __shared__ unsigned BsH[TBK * BSTR];   // 3200
    __shared__ unsigned BsL[TBK * BSTR];
    __shared__ float red[64 * 3];
    __shared__ float sbt1[128];
    __shared__ float sWt2[128 * 3];
    __shared__ float sbt2[3];

    const int tid  = threadIdx.x;
    const int lane = tid & 31;
    const int warp = tid >> 5;
    const int gid  = lane >> 2;     // 0..7
    const int tg   = lane & 3;      // 0..3
    const int wm   = warp >> 2;     // 0..1
    const int wn   = warp & 3;      // 0..3
    const int m0   = blockIdx.x * TBM;

    if (tid < 128) {
        sbt1[tid] = bt1[tid];
        sWt2[tid * 3 + 0] = Wt2[tid * 3 + 0];
        sWt2[tid * 3 + 1] = Wt2[tid * 3 + 1];
        sWt2[tid * 3 + 2] = Wt2[tid * 3 + 2];
    }
    if (tid < 3) sbt2[tid] = bt2[tid];
    if (tid < 192) red[tid] = 0.f;

    float4 acc[2][6];
#pragma unroll
    for (int i = 0; i < 2; i++)
#pragma unroll
        for (int j = 0; j < 6; j++) acc[i][j] = make_float4(0.f, 0.f, 0.f, 0.f);

    for (int kb = 0; kb < NH; kb += TBK) {
        // ---- stage A tile 64x16 (one float4 per thread), hi/lo split ----
        {
            int row = tid >> 2, c4 = tid & 3;
            int m = m0 + row; if (m > M - 1) m = M - 1;
            float4 v = *reinterpret_cast<const float4*>(A + (size_t)m * NH + kb + c4 * 4);
            unsigned* dh = &AsH[row * ASTR + c4 * 4];
            unsigned* dl = &AsL[row * ASTR + c4 * 4];
            split_tf32(v.x, dh[0], dl[0]);
            split_tf32(v.y, dh[1], dl[1]);
            split_tf32(v.z, dh[2], dl[2]);
            split_tf32(v.w, dh[3], dl[3]);
        }
        // ---- stage B tile 16x192 = [Wt1 | Ws | Wd], hi/lo split ----
#pragma unroll
        for (int i = 0; i < 3; i++) {
            int idx = tid + 256 * i;           // 0..767
            int row = idx / 48, q = idx - row * 48;
            float4 v;
            if (q < 32)      v = *reinterpret_cast<const float4*>(Wt1 + (size_t)(kb + row) * 128 + q * 4);
            else if (q < 40) v = *reinterpret_cast<const float4*>(Wr1 + (size_t)(64 + kb + row) * 32 + (q - 32) * 4);
            else             v = *reinterpret_cast<const float4*>(Wr1 + (size_t)(320 + kb + row) * 32 + (q - 40) * 4);
            unsigned* dh = &BsH[row * BSTR + q * 4];
            unsigned* dl = &BsL[row * BSTR + q * 4];
            split_tf32(v.x, dh[0], dl[0]);
            split_tf32(v.y, dh[1], dl[1]);
            split_tf32(v.z, dh[2], dl[2]);
            split_tf32(v.w, dh[3], dl[3]);
        }
        __syncthreads();

#pragma unroll
        for (int k8 = 0; k8 < 2; k8++) {
            const int kc = k8 * 8 + tg;
            unsigned aH[2][4], aL[2][4];
#pragma unroll
            for (int mf = 0; mf < 2; mf++) {
                int mr = wm * 32 + mf * 16 + gid;
                aH[mf][0] = AsH[mr * ASTR + kc];
                aH[mf][1] = AsH[(mr + 8) * ASTR + kc];
                aH[mf][2] = AsH[mr * ASTR + kc + 4];
                aH[mf][3] = AsH[(mr + 8) * ASTR + kc + 4];
                aL[mf][0] = AsL[mr * ASTR + kc];
                aL[mf][1] = AsL[(mr + 8) * ASTR + kc];
                aL[mf][2] = AsL[mr * ASTR + kc + 4];
                aL[mf][3] = AsL[(mr + 8) * ASTR + kc + 4];
            }
#pragma unroll
            for (int nf = 0; nf < 6; nf++) {
                int n = wn * 48 + nf * 8 + gid;
                unsigned bH0 = BsH[kc * BSTR + n];
                unsigned bH1 = BsH[(kc + 4) * BSTR + n];
                unsigned bL0 = BsL[kc * BSTR + n];
                unsigned bL1 = BsL[(kc + 4) * BSTR + n];
#pragma unroll
                for (int mf = 0; mf < 2; mf++) {
                    mma_tf32(acc[mf][nf], aH[mf][0], aH[mf][1], aH[mf][2], aH[mf][3], bL0, bL1);
                    mma_tf32(acc[mf][nf], aL[mf][0], aL[mf][1], aL[mf][2], aL[mf][3], bH0, bH1);
                    mma_tf32(acc[mf][nf], aH[mf][0], aH[mf][1], aH[mf][2], aH[mf][3], bH0, bH1);
                }
            }
        }
        __syncthreads();
    }

    // ---- epilogue ----
    float p[2][2][3];   // [mf][half(row r0/r1)][xyz] torsion partials
#pragma unroll
    for (int i = 0; i < 2; i++)
#pragma unroll
        for (int h = 0; h < 2; h++)
            p[i][h][0] = p[i][h][1] = p[i][h][2] = 0.f;

#pragma unroll
    for (int mf = 0; mf < 2; mf++) {
#pragma unroll
        for (int nf = 0; nf < 6; nf++) {
            int c = wn * 48 + nf * 8 + 2 * tg;
            int rl0 = wm * 32 + mf * 16 + gid;
            float4 d = acc[mf][nf];
            if (c >= 128) {
                float* base; int cc;
                if (c < 160) { base = g_hs; cc = c - 128; }
                else         { base = g_hd; cc = c - 160; }
                int mA = m0 + rl0, mB = mA + 8;
                if (mA < M) *reinterpret_cast<float2*>(base + (size_t)mA * 32 + cc) = make_float2(d.x, d.y);
                if (mB < M) *reinterpret_cast<float2*>(base + (size_t)mB * 32 + cc) = make_float2(d.z, d.w);
            } else {
                float b0 = sbt1[c], b1 = sbt1[c + 1];
                float w00 = sWt2[c * 3 + 0], w01 = sWt2[c * 3 + 1], w02 = sWt2[c * 3 + 2];
                float w10 = sWt2[(c + 1) * 3 + 0], w11 = sWt2[(c + 1) * 3 + 1], w12 = sWt2[(c + 1) * 3 + 2];
                float h0 = d.x + b0; h0 = (h0 >= 0.f) ? h0 : 0.01f * h0;
                float h1 = d.y + b1; h1 = (h1 >= 0.f) ? h1 : 0.01f * h1;
                p[mf][0][0] = fmaf(h0, w00, fmaf(h1, w10, p[mf][0][0]));
                p[mf][0][1] = fmaf(h0, w01, fmaf(h1, w11, p[mf][0][1]));
                p[mf][0][2] = fmaf(h0, w02, fmaf(h1, w12, p[mf][0][2]));
                float h2 = d.z + b0; h2 = (h2 >= 0.f) ? h2 : 0.01f * h2;
                float h3 = d.w + b1; h3 = (h3 >= 0.f) ? h3 : 0.01f * h3;
                p[mf][1][0] = fmaf(h2, w00, fmaf(h3, w10, p[mf][1][0]));
                p[mf][1][1] = fmaf(h2, w01, fmaf(h3, w11, p[mf][1][1]));
                p[mf][1][2] = fmaf(h2, w02, fmaf(h3, w12, p[mf][1][2]));
            }
        }
    }
#pragma unroll
    for (int mf = 0; mf < 2; mf++)
#pragma unroll
        for (int h = 0; h < 2; h++)
#pragma unroll
            for (int j = 0; j < 3; j++) {
                float v = p[mf][h][j];
                v += __shfl_xor_sync(0xffffffffu, v, 1);
                v += __shfl_xor_sync(0xffffffffu, v, 2);
                p[mf][h][j] = v;
            }
    if (tg == 0 && wn < 3) {
#pragma unroll
        for (int mf = 0; mf < 2; mf++)
#pragma unroll
            for (int h = 0; h < 2; h++) {
                int rl = wm * 32 + mf * 16 + gid + 8 * h;
                atomicAdd(&red[rl * 3 + 0], p[mf][h][0]);
                atomicAdd(&red[rl * 3 + 1], p[mf][h][1]);
                atomicAdd(&red[rl * 3 + 2], p[mf][h][2]);
            }
    }
    __syncthreads();

    if (tid < 64) {
        int m = m0 + tid;
        if (m < M) {
            float t0 = red[tid * 3 + 0] + sbt2[0];
            float t1 = red[tid * 3 + 1] + sbt2[1];
            float t2 = red[tid * 3 + 2] + sbt2[2];
            float rho = sqrtf(t0 * t0 + t1 * t1 + t2 * t2);
            float inv = 1.0f / rho;
            float n0 = t0 * inv, n1 = t1 * inv, n2 = t2 * inv;
            float theta = (fabsf(n0) > fabsf(n1)) ? atan2f(n1, n0)
                                                  : (1.5707963267948966f - atan2f(n0, n1));
            float cz = fminf(fmaxf(n2, -1.0f + EPSV), 1.0f - EPSV);
            float phi = acosf(cz);
            out_torsion[(size_t)m * 3 + 0] = rho;
            out_torsion[(size_t)m * 3 + 1] = phi;
            out_torsion[(size_t)m * 3 + 2] = theta;
        }
    }
}

// ============================================================
// CSR build
// ============================================================
__global__ void init_kernel(const float* __restrict__ cart, int N)
{
    int n = blockIdx.x * blockDim.x + threadIdx.x;
    if (n >= N) return;
    g_cA[n] = make_float4(cart[n * 3 + 0], cart[n * 3 + 1], cart[n * 3 + 2], 0.f);
    g_deg[n] = 0;
}

__global__ void count_kernel(const int* __restrict__ eidx, int E)
{
    int e = blockIdx.x * blockDim.x + threadIdx.x;
    if (e >= E) return;
    atomicAdd(&g_deg[eidx[E + e]], 1);
}

__global__ void scan1_kernel(int N)
{
    __shared__ int s[256];
    int t = threadIdx.x;
    int n = blockIdx.x * 256 + t;
    int v = (n < N) ? g_deg[n] : 0;
    s[t] = v;
    __syncthreads();
#pragma unroll
    for (int o = 1; o < 256; o <<= 1) {
        int x = (t >= o) ? s[t - o] : 0;
        __syncthreads();
        s[t] += x;
        __syncthreads();
    }
    if (n < N) g_ptr[n] = s[t] - v;          // local exclusive
    if (t == 255) g_bsum[blockIdx.x] = s[255];
}

__global__ void scan2_kernel(int nb)
{
    __shared__ int s[256];
    int t = threadIdx.x;
    int v = (t < nb) ? g_bsum[t] : 0;
    s[t] = v;
    __syncthreads();
#pragma unroll
    for (int o = 1; o < 256; o <<= 1) {
        int x = (t >= o) ? s[t - o] : 0;
        __syncthreads();
        s[t] += x;
        __syncthreads();
    }
    if (t < nb) g_boff[t] = s[t] - v;        // exclusive
}

__global__ void scan3_kernel(int N)
{
    int n = blockIdx.x * blockDim.x + threadIdx.x;
    if (n >= N) return;
    int p = g_ptr[n] + g_boff[n >> 8];
    g_ptr[n] = p;
    g_cursor[n] = p;
}

__global__ void fill_kernel(const int* __restrict__ eidx, int E)
{
    int e = blockIdx.x * blockDim.x + threadIdx.x;
    if (e >= E) return;
    int s = eidx[e];
    int d = eidx[E + e];
    int slot = atomicAdd(&g_cursor[d], 1);
    reinterpret_cast<float*>(g_ecsr)[slot * 4 + 2] = __int_as_float(s);
    g_pos[e] = slot;
}

// ============================================================
// Kernel 2: edge MLP, register-tiled GEMM (256 edges/block, 128 threads,
// thread tile = 8 edges x 8 dims). Writes coef into CSR slots.
// ============================================================
#define EMLP_SMEM_FLOATS (256 * 68 + 64 * 32 + 64 + 34)

__global__ __launch_bounds__(128, 2)
void edge_mlp_kernel(const float* __restrict__ edge_emb,  // [E,64]
                     const float* __restrict__ Wr1,       // [576,32]
                     const float* __restrict__ br1,       // [32]
                     const float* __restrict__ Wr2,       // [32,2]
                     const float* __restrict__ br2,       // [2]
                     const int*   __restrict__ eidx,      // [2,E]
                     int E)
{
    extern __shared__ float sm[];
    float* Es   = sm;                      // 256 * 68 (padded rows)
    float* sWe  = sm + 256 * 68;           // 64 * 32
    float* sWr2 = sWe + 64 * 32;           // 64
    float* sb   = sWr2 + 64;               // 32 br1 + 2 br2

    const int tid = threadIdx.x;
    const int eb  = blockIdx.x * 256;

    for (int i = tid; i < 2048; i += 128) sWe[i] = Wr1[i];   // We = Wr1[0:64]
    if (tid < 64) sWr2[tid] = Wr2[tid];
    if (tid < 32) sb[tid] = br1[tid];
    if (tid < 2)  sb[32 + tid] = br2[tid];

    // stage 256 edge rows (coalesced float4)
#pragma unroll
    for (int i = 0; i < 32; i++) {
        int gid = tid + 128 * i;
        int e = gid >> 4, q = gid & 15;
        float4 v = *reinterpret_cast<const float4*>(edge_emb + (size_t)(eb + e) * 64 + q * 4);
        *reinterpret_cast<float4*>(Es + e * 68 + q * 4) = v;
    }
    __syncthreads();

    const int eg = tid >> 2;     // 0..31 : edge group
    const int dg = tid & 3;      // 0..3  : dim group (8 dims each)

    float acc[8][8];
#pragma unroll
    for (int i = 0; i < 8; i++)
#pragma unroll
        for (int j = 0; j < 8; j++) acc[i][j] = 0.f;

    int rowbase[8];
#pragma unroll
    for (int i = 0; i < 8; i++) rowbase[i] = (eg + 32 * i) * 68;

#pragma unroll 8
    for (int k = 0; k < 64; k++) {
        float4 b0 = *reinterpret_cast<float4*>(sWe + k * 32 + dg * 8);
        float4 b1 = *reinterpret_cast<float4*>(sWe + k * 32 + dg * 8 + 4);
        float a[8];
#pragma unroll
        for (int i = 0; i < 8; i++) a[i] = Es[rowbase[i] + k];
#pragma unroll
        for (int i = 0; i < 8; i++) {
            acc[i][0] = fmaf(a[i], b0.x, acc[i][0]);
            acc[i][1] = fmaf(a[i], b0.y, acc[i][1]);
            acc[i][2] = fmaf(a[i], b0.z, acc[i][2]);
            acc[i][3] = fmaf(a[i], b0.w, acc[i][3]);
            acc[i][4] = fmaf(a[i], b1.x, acc[i][4]);
            acc[i][5] = fmaf(a[i], b1.y, acc[i][5]);
            acc[i][6] = fmaf(a[i], b1.z, acc[i][6]);
            acc[i][7] = fmaf(a[i], b1.w, acc[i][7]);
        }
    }

    // epilogue
#pragma unroll
    for (int i = 0; i < 8; i++) {
        int ge = eb + eg + 32 * i;
        int s = eidx[ge];
        int d = eidx[E + ge];
        float4 hs0 = *reinterpret_cast<const float4*>(g_hs + s * 32 + dg * 8);
        float4 hs1 = *reinterpret_cast<const float4*>(g_hs + s * 32 + dg * 8 + 4);
        float4 hd0 = *reinterpret_cast<const float4*>(g_hd + d * 32 + dg * 8);
        float4 hd1 = *reinterpret_cast<const float4*>(g_hd + d * 32 + dg * 8 + 4);
        float add[8] = {hs0.x + hd0.x, hs0.y + hd0.y, hs0.z + hd0.z, hs0.w + hd0.w,
                        hs1.x + hd1.x, hs1.y + hd1.y, hs1.z + hd1.z, hs1.w + hd1.w};
        float v0 = 0.f, v1 = 0.f;
#pragma unroll
        for (int j = 0; j < 8; j++) {
            float h = acc[i][j] + add[j] + sb[dg * 8 + j];
            h = (h >= 0.f) ? h : 0.01f * h;
            v0 = fmaf(h, sWr2[(dg * 8 + j) * 2 + 0], v0);
            v1 = fmaf(h, sWr2[(dg * 8 + j) * 2 + 1], v1);
        }
        v0 += __shfl_xor_sync(0xffffffffu, v0, 1);
        v0 += __shfl_xor_sync(0xffffffffu, v0, 2);
        v1 += __shfl_xor_sync(0xffffffffu, v1, 1);
        v1 += __shfl_xor_sync(0xffffffffu, v1, 2);
        if (dg == 0) {
            float x = v0 + sb[32] + 1.0f;
            float elen = fmaxf(x, 0.f) + log1pf(expf(-fabsf(x)));
            float y = v1 + sb[33] - 2.0f;
            float sg = 1.0f / (1.0f + expf(-y));
            int slot = g_pos[ge];
            float* dst = reinterpret_cast<float*>(g_ecsr) + (size_t)slot * 4;
            dst[0] = elen;
            dst[1] = 2.0f * sg;
        }
    }
}

// ============================================================
// Refiner: one gather kernel per step (ping-pong buffers, no atomics)
// ============================================================
__global__ __launch_bounds__(256)
void refine_step_kernel(const float4* __restrict__ cin, float4* __restrict__ cout,
                        float* __restrict__ out_coords, int last, int N)
{
    int n = blockIdx.x * blockDim.x + threadIdx.x;
    if (n >= N) return;
    float4 c = cin[n];
    int p = g_ptr[n];
    int d = g_deg[n];
    float ax = 0.f, ay = 0.f, az = 0.f;
#pragma unroll 4
    for (int i = 0; i < d; i++) {
        float4 er = g_ecsr[p + i];
        int s = __float_as_int(er.z);
        float4 cs = cin[s];
        float dx = c.x - cs.x, dy = c.y - cs.y, dz = c.z - cs.z;
        float dist = sqrtf(dx * dx + dy * dy + dz * dz);
        float f = __fdividef(er.y * (er.x - dist), dist + EPSV);
        ax = fmaf(f, dx, ax);
        ay = fmaf(f, dy, ay);
        az = fmaf(f, dz, az);
    }
    float an = sqrtf(ax * ax + ay * ay + az * az) + EPSV;
    float sc = fminf(an, 0.5f) / an;
    c.x += ax * sc; c.y += ay * sc; c.z += az * sc;
    cout[n] = c;
    if (last) {
        out_coords[n * 3 + 0] = c.x;
        out_coords[n * 3 + 1] = c.y;
        out_coords[n * 3 + 2] = c.z;
    }
}

// ============================================================
// launch
// ============================================================
extern "C" void kernel_launch(void* const* d_in, const int* in_sizes, int n_in,
                              void* d_out, int out_size)
{
    const float* node_emb  = (const float*)d_in[0];
    const float* edge_emb  = (const float*)d_in[1];
    const float* cart_init = (const float*)d_in[2];
    const float* Wt1       = (const float*)d_in[3];
    const float* bt1       = (const float*)d_in[4];
    const float* Wt2       = (const float*)d_in[5];
    const float* bt2       = (const float*)d_in[6];
    const float* Wr1       = (const float*)d_in[7];
    const float* br1       = (const float*)d_in[8];
    const float* Wr2       = (const float*)d_in[9];
    const float* br2       = (const float*)d_in[10];
    const int*   eidx      = (const int*)d_in[11];

    const int M = in_sizes[0] / NH;        // 50000
    const int E = in_sizes[1] / EH;        // 800000

    float* out = (float*)d_out;
    float* out_coords  = out;
    float* out_torsion = out + (size_t)M * 3;

    static bool attr_set = false;
    if (!attr_set) {
        cudaFuncSetAttribute(edge_mlp_kernel, cudaFuncAttributeMaxDynamicSharedMemorySize,
                             EMLP_SMEM_FLOATS * 4);
        attr_set = true;
    }

    const int nb_nodes = (M + 255) / 256;
    const int nb_edges = (E + 255) / 256;

    // 1. node GEMM (3xTF32 tensor cores) + torsion head + hs/hd
    node_gemm_tc<<<(M + TBM - 1) / TBM, 256>>>(node_emb, Wt1, bt1, Wt2, bt2, Wr1,
                                               out_torsion, M);
    // 2. CSR build
    init_kernel<<<nb_nodes, 256>>>(cart_init, M);
    count_kernel<<<nb_edges, 256>>>(eidx, E);
    scan1_kernel<<<nb_nodes, 256>>>(M);
    scan2_kernel<<<1, 256>>>(nb_nodes);
    scan3_kernel<<<nb_nodes, 256>>>(M);
    fill_kernel<<<nb_edges, 256>>>(eidx, E);
    // 3. edge MLP -> coefficients into CSR slots
    edge_mlp_kernel<<<nb_edges, 128, EMLP_SMEM_FLOATS * 4>>>(edge_emb, Wr1, br1, Wr2, br2,
                                                             eidx, E);
    // 4. refiner (ping-pong)
    float4* bufs[2];
    cudaGetSymbolAddress((void**)&bufs[0], g_cA);
    cudaGetSymbolAddress((void**)&bufs[1], g_cB);
    for (int s = 0; s < NSTEPS; s++) {
        refine_step_kernel<<<nb_nodes, 256>>>(bufs[s & 1], bufs[(s + 1) & 1],
                                              out_coords, (s == NSTEPS - 1) ? 1 : 0, M);
    }
}

// round 5
// speedup vs baseline: 1.7996x; 1.0755x over previous
#include <cuda_runtime.h>
#include <cuda_bf16.h>
#include <math.h>

// ---------------- problem constants ----------------
#define NNODES   50000
#define NEDGES   800000
#define NH       256
#define EH       64
#define NSTEPS   10
#define EPSV     0.01f

// ---------------- scratch (device globals, no allocation) ----------------
__device__ float  g_hs[NNODES * 32];
__device__ float  g_hd[NNODES * 32];
__device__ int    g_deg[NNODES];
__device__ int    g_ptr[NNODES];
__device__ int    g_cursor[NNODES];
__device__ int    g_bsum[256];
__device__ int    g_boff[256];
__device__ float2 g_coef[NEDGES];
__device__ float4 g_ecsr[NEDGES];     // .x = elen, .y = 2*step, .z = src (bits)
__device__ float4 g_cA[NNODES];
__device__ float4 g_cB[NNODES];

// ============================================================
// tf32 mma helpers
// ============================================================
__device__ __forceinline__ unsigned f2tf32(float f)
{
    unsigned u;
    asm("cvt.rna.tf32.f32 %0, %1;" : "=r"(u) : "f"(f));
    return u;
}

__device__ __forceinline__ void split_tf32(float v, unsigned& hi, unsigned& lo)
{
    hi = f2tf32(v);
    lo = f2tf32(v - __uint_as_float(hi));
}

__device__ __forceinline__ void mma_tf32(float4& d,
                                         unsigned a0, unsigned a1, unsigned a2, unsigned a3,
                                         unsigned b0, unsigned b1)
{
    asm volatile("mma.sync.aligned.m16n8k8.row.col.f32.tf32.tf32.f32 "
                 "{%0,%1,%2,%3}, {%4,%5,%6,%7}, {%8,%9}, {%0,%1,%2,%3};"
                 : "+f"(d.x), "+f"(d.y), "+f"(d.z), "+f"(d.w)
                 : "r"(a0), "r"(a1), "r"(a2), "r"(a3), "r"(b0), "r"(b1));
}

// ============================================================
// Kernel 1: node GEMM via tensor cores (3xTF32 = fp32-accurate)
// C = node_emb @ [Wt1 | Ws | Wd]   (M x 256 x 192)
// ============================================================
#define TBM 64
#define TBN 192
#define TBK 16
#define ASTR 20
#define BSTR 200

__global__ __launch_bounds__(256)
void node_gemm_tc(const float* __restrict__ A,      // node_emb [M,256]
                  const float* __restrict__ Wt1,    // [256,128]
                  const float* __restrict__ bt1,    // [128]
                  const float* __restrict__ Wt2,    // [128,3]
                  const float* __restrict__ bt2,    // [3]
                  const float* __restrict__ Wr1,    // [576,32]
                  float* __restrict__ out_torsion,
                  int M)
{
    __shared__ unsigned AsH[TBM * ASTR];
    __shared__ unsigned AsL[TBM * ASTR];
    __shared__ unsigned BsH[TBK * BSTR];
    __shared__ unsigned BsL[TBK * BSTR];
    __shared__ float red[64 * 3];
    __shared__ float sbt1[128];
    __shared__ float sWt2[128 * 3];
    __shared__ float sbt2[3];

    const int tid  = threadIdx.x;
    const int lane = tid & 31;
    const int warp = tid >> 5;
    const int gid  = lane >> 2;
    const int tg   = lane & 3;
    const int wm   = warp >> 2;
    const int wn   = warp & 3;
    const int m0   = blockIdx.x * TBM;

    if (tid < 128) {
        sbt1[tid] = bt1[tid];
        sWt2[tid * 3 + 0] = Wt2[tid * 3 + 0];
        sWt2[tid * 3 + 1] = Wt2[tid * 3 + 1];
        sWt2[tid * 3 + 2] = Wt2[tid * 3 + 2];
    }
    if (tid < 3) sbt2[tid] = bt2[tid];
    if (tid < 192) red[tid] = 0.f;

    float4 acc[2][6];
#pragma unroll
    for (int i = 0; i < 2; i++)
#pragma unroll
        for (int j = 0; j < 6; j++) acc[i][j] = make_float4(0.f, 0.f, 0.f, 0.f);

    for (int kb = 0; kb < NH; kb += TBK) {
        {
            int row = tid >> 2, c4 = tid & 3;
            int m = m0 + row; if (m > M - 1) m = M - 1;
            float4 v = *reinterpret_cast<const float4*>(A + (size_t)m * NH + kb + c4 * 4);
            unsigned* dh = &AsH[row * ASTR + c4 * 4];
            unsigned* dl = &AsL[row * ASTR + c4 * 4];
            split_tf32(v.x, dh[0], dl[0]);
            split_tf32(v.y, dh[1], dl[1]);
            split_tf32(v.z, dh[2], dl[2]);
            split_tf32(v.w, dh[3], dl[3]);
        }
#pragma unroll
        for (int i = 0; i < 3; i++) {
            int idx = tid + 256 * i;
            int row = idx / 48, q = idx - row * 48;
            float4 v;
            if (q < 32)      v = *reinterpret_cast<const float4*>(Wt1 + (size_t)(kb + row) * 128 + q * 4);
            else if (q < 40) v = *reinterpret_cast<const float4*>(Wr1 + (size_t)(64 + kb + row) * 32 + (q - 32) * 4);
            else             v = *reinterpret_cast<const float4*>(Wr1 + (size_t)(320 + kb + row) * 32 + (q - 40) * 4);
            unsigned* dh = &BsH[row * BSTR + q * 4];
            unsigned* dl = &BsL[row * BSTR + q * 4];
            split_tf32(v.x, dh[0], dl[0]);
            split_tf32(v.y, dh[1], dl[1]);
            split_tf32(v.z, dh[2], dl[2]);
            split_tf32(v.w, dh[3], dl[3]);
        }
        __syncthreads();

#pragma unroll
        for (int k8 = 0; k8 < 2; k8++) {
            const int kc = k8 * 8 + tg;
            unsigned aH[2][4], aL[2][4];
#pragma unroll
            for (int mf = 0; mf < 2; mf++) {
                int mr = wm * 32 + mf * 16 + gid;
                aH[mf][0] = AsH[mr * ASTR + kc];
                aH[mf][1] = AsH[(mr + 8) * ASTR + kc];
                aH[mf][2] = AsH[mr * ASTR + kc + 4];
                aH[mf][3] = AsH[(mr + 8) * ASTR + kc + 4];
                aL[mf][0] = AsL[mr * ASTR + kc];
                aL[mf][1] = AsL[(mr + 8) * ASTR + kc];
                aL[mf][2] = AsL[mr * ASTR + kc + 4];
                aL[mf][3] = AsL[(mr + 8) * ASTR + kc + 4];
            }
#pragma unroll
            for (int nf = 0; nf < 6; nf++) {
                int n = wn * 48 + nf * 8 + gid;
                unsigned bH0 = BsH[kc * BSTR + n];
                unsigned bH1 = BsH[(kc + 4) * BSTR + n];
                unsigned bL0 = BsL[kc * BSTR + n];
                unsigned bL1 = BsL[(kc + 4) * BSTR + n];
#pragma unroll
                for (int mf = 0; mf < 2; mf++) {
                    mma_tf32(acc[mf][nf], aH[mf][0], aH[mf][1], aH[mf][2], aH[mf][3], bL0, bL1);
                    mma_tf32(acc[mf][nf], aL[mf][0], aL[mf][1], aL[mf][2], aL[mf][3], bH0, bH1);
                    mma_tf32(acc[mf][nf], aH[mf][0], aH[mf][1], aH[mf][2], aH[mf][3], bH0, bH1);
                }
            }
        }
        __syncthreads();
    }

    // ---- epilogue ----
    float p[2][2][3];
#pragma unroll
    for (int i = 0; i < 2; i++)
#pragma unroll
        for (int h = 0; h < 2; h++)
            p[i][h][0] = p[i][h][1] = p[i][h][2] = 0.f;

#pragma unroll
    for (int mf = 0; mf < 2; mf++) {
#pragma unroll
        for (int nf = 0; nf < 6; nf++) {
            int c = wn * 48 + nf * 8 + 2 * tg;
            int rl0 = wm * 32 + mf * 16 + gid;
            float4 d = acc[mf][nf];
            if (c >= 128) {
                float* base; int cc;
                if (c < 160) { base = g_hs; cc = c - 128; }
                else         { base = g_hd; cc = c - 160; }
                int mA = m0 + rl0, mB = mA + 8;
                if (mA < M) *reinterpret_cast<float2*>(base + (size_t)mA * 32 + cc) = make_float2(d.x, d.y);
                if (mB < M) *reinterpret_cast<float2*>(base + (size_t)mB * 32 + cc) = make_float2(d.z, d.w);
            } else {
                float b0 = sbt1[c], b1 = sbt1[c + 1];
                float w00 = sWt2[c * 3 + 0], w01 = sWt2[c * 3 + 1], w02 = sWt2[c * 3 + 2];
                float w10 = sWt2[(c + 1) * 3 + 0], w11 = sWt2[(c + 1) * 3 + 1], w12 = sWt2[(c + 1) * 3 + 2];
                float h0 = d.x + b0; h0 = (h0 >= 0.f) ? h0 : 0.01f * h0;
                float h1 = d.y + b1; h1 = (h1 >= 0.f) ? h1 : 0.01f * h1;
                p[mf][0][0] = fmaf(h0, w00, fmaf(h1, w10, p[mf][0][0]));
                p[mf][0][1] = fmaf(h0, w01, fmaf(h1, w11, p[mf][0][1]));
                p[mf][0][2] = fmaf(h0, w02, fmaf(h1, w12, p[mf][0][2]));
                float h2 = d.z + b0; h2 = (h2 >= 0.f) ? h2 : 0.01f * h2;
                float h3 = d.w + b1; h3 = (h3 >= 0.f) ? h3 : 0.01f * h3;
                p[mf][1][0] = fmaf(h2, w00, fmaf(h3, w10, p[mf][1][0]));
                p[mf][1][1] = fmaf(h2, w01, fmaf(h3, w11, p[mf][1][1]));
                p[mf][1][2] = fmaf(h2, w02, fmaf(h3, w12, p[mf][1][2]));
            }
        }
    }
#pragma unroll
    for (int mf = 0; mf < 2; mf++)
#pragma unroll
        for (int h = 0; h < 2; h++)
#pragma unroll
            for (int j = 0; j < 3; j++) {
                float v = p[mf][h][j];
                v += __shfl_xor_sync(0xffffffffu, v, 1);
                v += __shfl_xor_sync(0xffffffffu, v, 2);
                p[mf][h][j] = v;
            }
    if (tg == 0 && wn < 3) {
#pragma unroll
        for (int mf = 0; mf < 2; mf++)
#pragma unroll
            for (int h = 0; h < 2; h++) {
                int rl = wm * 32 + mf * 16 + gid + 8 * h;
                atomicAdd(&red[rl * 3 + 0], p[mf][h][0]);
                atomicAdd(&red[rl * 3 + 1], p[mf][h][1]);
                atomicAdd(&red[rl * 3 + 2], p[mf][h][2]);
            }
    }
    __syncthreads();

    if (tid < 64) {
        int m = m0 + tid;
        if (m < M) {
            float t0 = red[tid * 3 + 0] + sbt2[0];
            float t1 = red[tid * 3 + 1] + sbt2[1];
            float t2 = red[tid * 3 + 2] + sbt2[2];
            float rho = sqrtf(t0 * t0 + t1 * t1 + t2 * t2);
            float inv = 1.0f / rho;
            float n0 = t0 * inv, n1 = t1 * inv, n2 = t2 * inv;
            float theta = (fabsf(n0) > fabsf(n1)) ? atan2f(n1, n0)
                                                  : (1.5707963267948966f - atan2f(n0, n1));
            float cz = fminf(fmaxf(n2, -1.0f + EPSV), 1.0f - EPSV);
            float phi = acosf(cz);
            out_torsion[(size_t)m * 3 + 0] = rho;
            out_torsion[(size_t)m * 3 + 1] = phi;
            out_torsion[(size_t)m * 3 + 2] = theta;
        }
    }
}

// ============================================================
// CSR build
// ============================================================
__global__ void init_kernel(const float* __restrict__ cart, int N)
{
    int n = blockIdx.x * blockDim.x + threadIdx.x;
    if (n >= N) return;
    g_cA[n] = make_float4(cart[n * 3 + 0], cart[n * 3 + 1], cart[n * 3 + 2], 0.f);
    g_deg[n] = 0;
}

__global__ void count_kernel(const int* __restrict__ eidx, int E)
{
    int e = blockIdx.x * blockDim.x + threadIdx.x;
    if (e >= E) return;
    atomicAdd(&g_deg[eidx[E + e]], 1);
}

__global__ void scan1_kernel(int N)
{
    __shared__ int s[256];
    int t = threadIdx.x;
    int n = blockIdx.x * 256 + t;
    int v = (n < N) ? g_deg[n] : 0;
    s[t] = v;
    __syncthreads();
#pragma unroll
    for (int o = 1; o < 256; o <<= 1) {
        int x = (t >= o) ? s[t - o] : 0;
        __syncthreads();
        s[t] += x;
        __syncthreads();
    }
    if (n < N) g_ptr[n] = s[t] - v;
    if (t == 255) g_bsum[blockIdx.x] = s[255];
}

__global__ void scan2_kernel(int nb)
{
    __shared__ int s[256];
    int t = threadIdx.x;
    int v = (t < nb) ? g_bsum[t] : 0;
    s[t] = v;
    __syncthreads();
#pragma unroll
    for (int o = 1; o < 256; o <<= 1) {
        int x = (t >= o) ? s[t - o] : 0;
        __syncthreads();
        s[t] += x;
        __syncthreads();
    }
    if (t < nb) g_boff[t] = s[t] - v;
}

__global__ void scan3_kernel(int N)
{
    int n = blockIdx.x * blockDim.x + threadIdx.x;
    if (n >= N) return;
    int p = g_ptr[n] + g_boff[n >> 8];
    g_ptr[n] = p;
    g_cursor[n] = p;
}

// fill: merge per-edge coef + src into CSR slot (full 16B store)
__global__ void fill_kernel(const int* __restrict__ eidx, int E)
{
    int e = blockIdx.x * blockDim.x + threadIdx.x;
    if (e >= E) return;
    int s = eidx[e];
    int d = eidx[E + e];
    float2 cf = g_coef[e];
    int slot = atomicAdd(&g_cursor[d], 1);
    g_ecsr[slot] = make_float4(cf.x, cf.y, __int_as_float(s), 0.f);
}

// ============================================================
// Kernel 2: edge MLP -> g_coef[e] = (elen, 2*step)
// ============================================================
#define EMLP_SMEM_FLOATS (256 * 68 + 64 * 32 + 64 + 34)

__global__ __launch_bounds__(128, 2)
void edge_mlp_kernel(const float* __restrict__ edge_emb,  // [E,64]
                     const float* __restrict__ Wr1,       // [576,32]
                     const float* __restrict__ br1,       // [32]
                     const float* __restrict__ Wr2,       // [32,2]
                     const float* __restrict__ br2,       // [2]
                     const int*   __restrict__ eidx,      // [2,E]
                     int E)
{
    extern __shared__ float sm[];
    float* Es   = sm;                      // 256 * 68 (padded rows)
    float* sWe  = sm + 256 * 68;           // 64 * 32
    float* sWr2 = sWe + 64 * 32;           // 64
    float* sb   = sWr2 + 64;               // 32 br1 + 2 br2

    const int tid = threadIdx.x;
    const int eb  = blockIdx.x * 256;

    for (int i = tid; i < 2048; i += 128) sWe[i] = Wr1[i];
    if (tid < 64) sWr2[tid] = Wr2[tid];
    if (tid < 32) sb[tid] = br1[tid];
    if (tid < 2)  sb[32 + tid] = br2[tid];

#pragma unroll
    for (int i = 0; i < 32; i++) {
        int gid = tid + 128 * i;
        int e = gid >> 4, q = gid & 15;
        float4 v = *reinterpret_cast<const float4*>(edge_emb + (size_t)(eb + e) * 64 + q * 4);
        *reinterpret_cast<float4*>(Es + e * 68 + q * 4) = v;
    }
    __syncthreads();

    const int eg = tid >> 2;
    const int dg = tid & 3;

    float acc[8][8];
#pragma unroll
    for (int i = 0; i < 8; i++)
#pragma unroll
        for (int j = 0; j < 8; j++) acc[i][j] = 0.f;

    int rowbase[8];
#pragma unroll
    for (int i = 0; i < 8; i++) rowbase[i] = (eg + 32 * i) * 68;

#pragma unroll 8
    for (int k = 0; k < 64; k++) {
        float4 b0 = *reinterpret_cast<float4*>(sWe + k * 32 + dg * 8);
        float4 b1 = *reinterpret_cast<float4*>(sWe + k * 32 + dg * 8 + 4);
        float a[8];
#pragma unroll
        for (int i = 0; i < 8; i++) a[i] = Es[rowbase[i] + k];
#pragma unroll
        for (int i = 0; i < 8; i++) {
            acc[i][0] = fmaf(a[i], b0.x, acc[i][0]);
            acc[i][1] = fmaf(a[i], b0.y, acc[i][1]);
            acc[i][2] = fmaf(a[i], b0.z, acc[i][2]);
            acc[i][3] = fmaf(a[i], b0.w, acc[i][3]);
            acc[i][4] = fmaf(a[i], b1.x, acc[i][4]);
            acc[i][5] = fmaf(a[i], b1.y, acc[i][5]);
            acc[i][6] = fmaf(a[i], b1.z, acc[i][6]);
            acc[i][7] = fmaf(a[i], b1.w, acc[i][7]);
        }
    }

    // epilogue
#pragma unroll
    for (int i = 0; i < 8; i++) {
        int ge = eb + eg + 32 * i;
        int s = eidx[ge];
        int d = eidx[E + ge];
        float4 hs0 = *reinterpret_cast<const float4*>(g_hs + s * 32 + dg * 8);
        float4 hs1 = *reinterpret_cast<const float4*>(g_hs + s * 32 + dg * 8 + 4);
        float4 hd0 = *reinterpret_cast<const float4*>(g_hd + d * 32 + dg * 8);
        float4 hd1 = *reinterpret_cast<const float4*>(g_hd + d * 32 + dg * 8 + 4);
        float add[8] = {hs0.x + hd0.x, hs0.y + hd0.y, hs0.z + hd0.z, hs0.w + hd0.w,
                        hs1.x + hd1.x, hs1.y + hd1.y, hs1.z + hd1.z, hs1.w + hd1.w};
        float v0 = 0.f, v1 = 0.f;
#pragma unroll
        for (int j = 0; j < 8; j++) {
            float h = acc[i][j] + add[j] + sb[dg * 8 + j];
            h = (h >= 0.f) ? h : 0.01f * h;
            v0 = fmaf(h, sWr2[(dg * 8 + j) * 2 + 0], v0);
            v1 = fmaf(h, sWr2[(dg * 8 + j) * 2 + 1], v1);
        }
        v0 += __shfl_xor_sync(0xffffffffu, v0, 1);
        v0 += __shfl_xor_sync(0xffffffffu, v0, 2);
        v1 += __shfl_xor_sync(0xffffffffu, v1, 1);
        v1 += __shfl_xor_sync(0xffffffffu, v1, 2);
        if (dg == 0) {
            float x = v0 + sb[32] + 1.0f;
            float elen = fmaxf(x, 0.f) + log1pf(expf(-fabsf(x)));
            float y = v1 + sb[33] - 2.0f;
            float sg = 1.0f / (1.0f + expf(-y));
            g_coef[ge] = make_float2(elen, 2.0f * sg);
        }
    }
}

// ============================================================
// Refiner: one gather kernel per step (ping-pong buffers, no atomics)
// ============================================================
__global__ __launch_bounds__(256)
void refine_step_kernel(const float4* __restrict__ cin, float4* __restrict__ cout,
                        float* __restrict__ out_coords, int last, int N)
{
    int n = blockIdx.x * blockDim.x + threadIdx.x;
    if (n >= N) return;
    float4 c = cin[n];
    int p = g_ptr[n];
    int d = g_deg[n];
    float ax = 0.f, ay = 0.f, az = 0.f;
#pragma unroll 4
    for (int i = 0; i < d; i++) {
        float4 er = g_ecsr[p + i];
        int s = __float_as_int(er.z);
        float4 cs = cin[s];
        float dx = c.x - cs.x, dy = c.y - cs.y, dz = c.z - cs.z;
        float dist = sqrtf(dx * dx + dy * dy + dz * dz);
        float f = __fdividef(er.y * (er.x - dist), dist + EPSV);
        ax = fmaf(f, dx, ax);
        ay = fmaf(f, dy, ay);
        az = fmaf(f, dz, az);
    }
    float an = sqrtf(ax * ax + ay * ay + az * az) + EPSV;
    float sc = fminf(an, 0.5f) / an;
    c.x += ax * sc; c.y += ay * sc; c.z += az * sc;
    cout[n] = c;
    if (last) {
        out_coords[n * 3 + 0] = c.x;
        out_coords[n * 3 + 1] = c.y;
        out_coords[n * 3 + 2] = c.z;
    }
}

// ============================================================
// launch — two-stream fork/join (graph-capturable)
// ============================================================
extern "C" void kernel_launch(void* const* d_in, const int* in_sizes, int n_in,
                              void* d_out, int out_size)
{
    const float* node_emb  = (const float*)d_in[0];
    const float* edge_emb  = (const float*)d_in[1];
    const float* cart_init = (const float*)d_in[2];
    const float* Wt1       = (const float*)d_in[3];
    const float* bt1       = (const float*)d_in[4];
    const float* Wt2       = (const float*)d_in[5];
    const float* bt2       = (const float*)d_in[6];
    const float* Wr1       = (const float*)d_in[7];
    const float* br1       = (const float*)d_in[8];
    const float* Wr2       = (const float*)d_in[9];
    const float* br2       = (const float*)d_in[10];
    const int*   eidx      = (const int*)d_in[11];

    const int M = in_sizes[0] / NH;        // 50000
    const int E = in_sizes[1] / EH;        // 800000

    float* out = (float*)d_out;
    float* out_coords  = out;
    float* out_torsion = out + (size_t)M * 3;

    static cudaStream_t s2 = nullptr;
    static cudaEvent_t evFork = nullptr, evJoin = nullptr;
    if (!s2) {
        cudaStreamCreateWithFlags(&s2, cudaStreamNonBlocking);
        cudaEventCreateWithFlags(&evFork, cudaEventDisableTiming);
        cudaEventCreateWithFlags(&evJoin, cudaEventDisableTiming);
        cudaFuncSetAttribute(edge_mlp_kernel, cudaFuncAttributeMaxDynamicSharedMemorySize,
                             EMLP_SMEM_FLOATS * 4);
    }

    const int nb_nodes = (M + 255) / 256;
    const int nb_edges = (E + 255) / 256;

    // fork: CSR-build chain on side stream s2
    cudaEventRecord(evFork, 0);
    cudaStreamWaitEvent(s2, evFork, 0);

    // --- call order chosen so capture index 3 = edge_mlp (profiled) ---
    init_kernel<<<nb_nodes, 256, 0, s2>>>(cart_init, M);                         // 0
    count_kernel<<<nb_edges, 256, 0, s2>>>(eidx, E);                             // 1
    node_gemm_tc<<<(M + TBM - 1) / TBM, 256>>>(node_emb, Wt1, bt1, Wt2, bt2,     // 2
                                               Wr1, out_torsion, M);
    edge_mlp_kernel<<<nb_edges, 128, EMLP_SMEM_FLOATS * 4>>>(edge_emb, Wr1, br1, // 3
                                                             Wr2, br2, eidx, E);
    scan1_kernel<<<nb_nodes, 256, 0, s2>>>(M);                                   // 4
    scan2_kernel<<<1, 256, 0, s2>>>(nb_nodes);                                   // 5
    scan3_kernel<<<nb_nodes, 256, 0, s2>>>(M);                                   // 6

    // join: fill needs cursor (s2) + coef (stream 0)
    cudaEventRecord(evJoin, s2);
    cudaStreamWaitEvent(0, evJoin, 0);

    fill_kernel<<<nb_edges, 256>>>(eidx, E);                                     // 7

    float4* bufs[2];
    cudaGetSymbolAddress((void**)&bufs[0], g_cA);
    cudaGetSymbolAddress((void**)&bufs[1], g_cB);
    for (int s = 0; s < NSTEPS; s++) {
        refine_step_kernel<<<nb_nodes, 256>>>(bufs[s & 1], bufs[(s + 1) & 1],
                                              out_coords, (s == NSTEPS - 1) ? 1 : 0, M);
    }
}

// round 6
// speedup vs baseline: 1.9630x; 1.0908x over previous
#include <cuda_runtime.h>
#include <cuda_bf16.h>
#include <math.h>

// ---------------- problem constants ----------------
#define NNODES   50000
#define NEDGES   800000
#define NH       256
#define EH       64
#define NSTEPS   10
#define EPSV     0.01f

// ---------------- scratch (device globals, no allocation) ----------------
__device__ float  g_hs[NNODES * 32];
__device__ float  g_hd[NNODES * 32];
__device__ int    g_deg[NNODES];
__device__ int    g_ptr[NNODES];
__device__ int    g_cursor[NNODES];
__device__ int    g_bsum[256];
__device__ int    g_boff[256];
__device__ float2 g_coef[NEDGES];
__device__ float4 g_ecsr[NEDGES];     // .x = elen, .y = 2*step, .z = src (bits)
__device__ float4 g_cA[NNODES];
__device__ float4 g_cB[NNODES];

// ============================================================
// tf32 mma helpers
// ============================================================
__device__ __forceinline__ unsigned f2tf32(float f)
{
    unsigned u;
    asm("cvt.rna.tf32.f32 %0, %1;" : "=r"(u) : "f"(f));
    return u;
}

__device__ __forceinline__ void split_tf32(float v, unsigned& hi, unsigned& lo)
{
    hi = f2tf32(v);
    lo = f2tf32(v - __uint_as_float(hi));
}

__device__ __forceinline__ void mma_tf32(float4& d,
                                         unsigned a0, unsigned a1, unsigned a2, unsigned a3,
                                         unsigned b0, unsigned b1)
{
    asm volatile("mma.sync.aligned.m16n8k8.row.col.f32.tf32.tf32.f32 "
                 "{%0,%1,%2,%3}, {%4,%5,%6,%7}, {%8,%9}, {%0,%1,%2,%3};"
                 : "+f"(d.x), "+f"(d.y), "+f"(d.z), "+f"(d.w)
                 : "r"(a0), "r"(a1), "r"(a2), "r"(a3), "r"(b0), "r"(b1));
}

// ============================================================
// Kernel 1: node GEMM via tensor cores (3xTF32 = fp32-accurate)
// C = node_emb @ [Wt1 | Ws | Wd]   (M x 256 x 192)
// ============================================================
#define TBM 64
#define TBN 192
#define TBK 16
#define ASTR 20
#define BSTR 200

__global__ __launch_bounds__(256)
void node_gemm_tc(const float* __restrict__ A,      // node_emb [M,256]
                  const float* __restrict__ Wt1,    // [256,128]
                  const float* __restrict__ bt1,    // [128]
                  const float* __restrict__ Wt2,    // [128,3]
                  const float* __restrict__ bt2,    // [3]
                  const float* __restrict__ Wr1,    // [576,32]
                  float* __restrict__ out_torsion,
                  int M)
{
    __shared__ unsigned AsH[TBM * ASTR];
    __shared__ unsigned AsL[TBM * ASTR];
    __shared__ unsigned BsH[TBK * BSTR];
    __shared__ unsigned BsL[TBK * BSTR];
    __shared__ float red[64 * 3];
    __shared__ float sbt1[128];
    __shared__ float sWt2[128 * 3];
    __shared__ float sbt2[3];

    const int tid  = threadIdx.x;
    const int lane = tid & 31;
    const int warp = tid >> 5;
    const int gid  = lane >> 2;
    const int tg   = lane & 3;
    const int wm   = warp >> 2;
    const int wn   = warp & 3;
    const int m0   = blockIdx.x * TBM;

    if (tid < 128) {
        sbt1[tid] = bt1[tid];
        sWt2[tid * 3 + 0] = Wt2[tid * 3 + 0];
        sWt2[tid * 3 + 1] = Wt2[tid * 3 + 1];
        sWt2[tid * 3 + 2] = Wt2[tid * 3 + 2];
    }
    if (tid < 3) sbt2[tid] = bt2[tid];
    if (tid < 192) red[tid] = 0.f;

    float4 acc[2][6];
#pragma unroll
    for (int i = 0; i < 2; i++)
#pragma unroll
        for (int j = 0; j < 6; j++) acc[i][j] = make_float4(0.f, 0.f, 0.f, 0.f);

    for (int kb = 0; kb < NH; kb += TBK) {
        {
            int row = tid >> 2, c4 = tid & 3;
            int m = m0 + row; if (m > M - 1) m = M - 1;
            float4 v = *reinterpret_cast<const float4*>(A + (size_t)m * NH + kb + c4 * 4);
            unsigned* dh = &AsH[row * ASTR + c4 * 4];
            unsigned* dl = &AsL[row * ASTR + c4 * 4];
            split_tf32(v.x, dh[0], dl[0]);
            split_tf32(v.y, dh[1], dl[1]);
            split_tf32(v.z, dh[2], dl[2]);
            split_tf32(v.w, dh[3], dl[3]);
        }
#pragma unroll
        for (int i = 0; i < 3; i++) {
            int idx = tid + 256 * i;
            int row = idx / 48, q = idx - row * 48;
            float4 v;
            if (q < 32)      v = *reinterpret_cast<const float4*>(Wt1 + (size_t)(kb + row) * 128 + q * 4);
            else if (q < 40) v = *reinterpret_cast<const float4*>(Wr1 + (size_t)(64 + kb + row) * 32 + (q - 32) * 4);
            else             v = *reinterpret_cast<const float4*>(Wr1 + (size_t)(320 + kb + row) * 32 + (q - 40) * 4);
            unsigned* dh = &BsH[row * BSTR + q * 4];
            unsigned* dl = &BsL[row * BSTR + q * 4];
            split_tf32(v.x, dh[0], dl[0]);
            split_tf32(v.y, dh[1], dl[1]);
            split_tf32(v.z, dh[2], dl[2]);
            split_tf32(v.w, dh[3], dl[3]);
        }
        __syncthreads();

#pragma unroll
        for (int k8 = 0; k8 < 2; k8++) {
            const int kc = k8 * 8 + tg;
            unsigned aH[2][4], aL[2][4];
#pragma unroll
            for (int mf = 0; mf < 2; mf++) {
                int mr = wm * 32 + mf * 16 + gid;
                aH[mf][0] = AsH[mr * ASTR + kc];
                aH[mf][1] = AsH[(mr + 8) * ASTR + kc];
                aH[mf][2] = AsH[mr * ASTR + kc + 4];
                aH[mf][3] = AsH[(mr + 8) * ASTR + kc + 4];
                aL[mf][0] = AsL[mr * ASTR + kc];
                aL[mf][1] = AsL[(mr + 8) * ASTR + kc];
                aL[mf][2] = AsL[mr * ASTR + kc + 4];
                aL[mf][3] = AsL[(mr + 8) * ASTR + kc + 4];
            }
#pragma unroll
            for (int nf = 0; nf < 6; nf++) {
                int n = wn * 48 + nf * 8 + gid;
                unsigned bH0 = BsH[kc * BSTR + n];
                unsigned bH1 = BsH[(kc + 4) * BSTR + n];
                unsigned bL0 = BsL[kc * BSTR + n];
                unsigned bL1 = BsL[(kc + 4) * BSTR + n];
#pragma unroll
                for (int mf = 0; mf < 2; mf++) {
                    mma_tf32(acc[mf][nf], aH[mf][0], aH[mf][1], aH[mf][2], aH[mf][3], bL0, bL1);
                    mma_tf32(acc[mf][nf], aL[mf][0], aL[mf][1], aL[mf][2], aL[mf][3], bH0, bH1);
                    mma_tf32(acc[mf][nf], aH[mf][0], aH[mf][1], aH[mf][2], aH[mf][3], bH0, bH1);
                }
            }
        }
        __syncthreads();
    }

    // ---- epilogue ----
    float p[2][2][3];
#pragma unroll
    for (int i = 0; i < 2; i++)
#pragma unroll
        for (int h = 0; h < 2; h++)
            p[i][h][0] = p[i][h][1] = p[i][h][2] = 0.f;

#pragma unroll
    for (int mf = 0; mf < 2; mf++) {
#pragma unroll
        for (int nf = 0; nf < 6; nf++) {
            int c = wn * 48 + nf * 8 + 2 * tg;
            int rl0 = wm * 32 + mf * 16 + gid;
            float4 d = acc[mf][nf];
            if (c >= 128) {
                float* base; int cc;
                if (c < 160) { base = g_hs; cc = c - 128; }
                else         { base = g_hd; cc = c - 160; }
                int mA = m0 + rl0, mB = mA + 8;
                if (mA < M) *reinterpret_cast<float2*>(base + (size_t)mA * 32 + cc) = make_float2(d.x, d.y);
                if (mB < M) *reinterpret_cast<float2*>(base + (size_t)mB * 32 + cc) = make_float2(d.z, d.w);
            } else {
                float b0 = sbt1[c], b1 = sbt1[c + 1];
                float w00 = sWt2[c * 3 + 0], w01 = sWt2[c * 3 + 1], w02 = sWt2[c * 3 + 2];
                float w10 = sWt2[(c + 1) * 3 + 0], w11 = sWt2[(c + 1) * 3 + 1], w12 = sWt2[(c + 1) * 3 + 2];
                float h0 = d.x + b0; h0 = (h0 >= 0.f) ? h0 : 0.01f * h0;
                float h1 = d.y + b1; h1 = (h1 >= 0.f) ? h1 : 0.01f * h1;
                p[mf][0][0] = fmaf(h0, w00, fmaf(h1, w10, p[mf][0][0]));
                p[mf][0][1] = fmaf(h0, w01, fmaf(h1, w11, p[mf][0][1]));
                p[mf][0][2] = fmaf(h0, w02, fmaf(h1, w12, p[mf][0][2]));
                float h2 = d.z + b0; h2 = (h2 >= 0.f) ? h2 : 0.01f * h2;
                float h3 = d.w + b1; h3 = (h3 >= 0.f) ? h3 : 0.01f * h3;
                p[mf][1][0] = fmaf(h2, w00, fmaf(h3, w10, p[mf][1][0]));
                p[mf][1][1] = fmaf(h2, w01, fmaf(h3, w11, p[mf][1][1]));
                p[mf][1][2] = fmaf(h2, w02, fmaf(h3, w12, p[mf][1][2]));
            }
        }
    }
#pragma unroll
    for (int mf = 0; mf < 2; mf++)
#pragma unroll
        for (int h = 0; h < 2; h++)
#pragma unroll
            for (int j = 0; j < 3; j++) {
                float v = p[mf][h][j];
                v += __shfl_xor_sync(0xffffffffu, v, 1);
                v += __shfl_xor_sync(0xffffffffu, v, 2);
                p[mf][h][j] = v;
            }
    if (tg == 0 && wn < 3) {
#pragma unroll
        for (int mf = 0; mf < 2; mf++)
#pragma unroll
            for (int h = 0; h < 2; h++) {
                int rl = wm * 32 + mf * 16 + gid + 8 * h;
                atomicAdd(&red[rl * 3 + 0], p[mf][h][0]);
                atomicAdd(&red[rl * 3 + 1], p[mf][h][1]);
                atomicAdd(&red[rl * 3 + 2], p[mf][h][2]);
            }
    }
    __syncthreads();

    if (tid < 64) {
        int m = m0 + tid;
        if (m < M) {
            float t0 = red[tid * 3 + 0] + sbt2[0];
            float t1 = red[tid * 3 + 1] + sbt2[1];
            float t2 = red[tid * 3 + 2] + sbt2[2];
            float rho = sqrtf(t0 * t0 + t1 * t1 + t2 * t2);
            float inv = 1.0f / rho;
            float n0 = t0 * inv, n1 = t1 * inv, n2 = t2 * inv;
            float theta = (fabsf(n0) > fabsf(n1)) ? atan2f(n1, n0)
                                                  : (1.5707963267948966f - atan2f(n0, n1));
            float cz = fminf(fmaxf(n2, -1.0f + EPSV), 1.0f - EPSV);
            float phi = acosf(cz);
            out_torsion[(size_t)m * 3 + 0] = rho;
            out_torsion[(size_t)m * 3 + 1] = phi;
            out_torsion[(size_t)m * 3 + 2] = theta;
        }
    }
}

// ============================================================
// CSR build
// ============================================================
__global__ void init_kernel(const float* __restrict__ cart, int N)
{
    int n = blockIdx.x * blockDim.x + threadIdx.x;
    if (n >= N) return;
    g_cA[n] = make_float4(cart[n * 3 + 0], cart[n * 3 + 1], cart[n * 3 + 2], 0.f);
    g_deg[n] = 0;
}

__global__ void count_kernel(const int* __restrict__ eidx, int E)
{
    int e = blockIdx.x * blockDim.x + threadIdx.x;
    if (e >= E) return;
    atomicAdd(&g_deg[eidx[E + e]], 1);
}

__global__ void scan1_kernel(int N)
{
    __shared__ int s[256];
    int t = threadIdx.x;
    int n = blockIdx.x * 256 + t;
    int v = (n < N) ? g_deg[n] : 0;
    s[t] = v;
    __syncthreads();
#pragma unroll
    for (int o = 1; o < 256; o <<= 1) {
        int x = (t >= o) ? s[t - o] : 0;
        __syncthreads();
        s[t] += x;
        __syncthreads();
    }
    if (n < N) g_ptr[n] = s[t] - v;
    if (t == 255) g_bsum[blockIdx.x] = s[255];
}

__global__ void scan2_kernel(int nb)
{
    __shared__ int s[256];
    int t = threadIdx.x;
    int v = (t < nb) ? g_bsum[t] : 0;
    s[t] = v;
    __syncthreads();
#pragma unroll
    for (int o = 1; o < 256; o <<= 1) {
        int x = (t >= o) ? s[t - o] : 0;
        __syncthreads();
        s[t] += x;
        __syncthreads();
    }
    if (t < nb) g_boff[t] = s[t] - v;
}

__global__ void scan3_kernel(int N)
{
    int n = blockIdx.x * blockDim.x + threadIdx.x;
    if (n >= N) return;
    int p = g_ptr[n] + g_boff[n >> 8];
    g_ptr[n] = p;
    g_cursor[n] = p;
}

// fill: merge per-edge coef + src into CSR slot (full 16B store)
__global__ void fill_kernel(const int* __restrict__ eidx, int E)
{
    int e = blockIdx.x * blockDim.x + threadIdx.x;
    if (e >= E) return;
    int s = eidx[e];
    int d = eidx[E + e];
    float2 cf = g_coef[e];
    int slot = atomicAdd(&g_cursor[d], 1);
    g_ecsr[slot] = make_float4(cf.x, cf.y, __int_as_float(s), 0.f);
}

// ============================================================
// Kernel 2: edge MLP -> g_coef[e] = (elen, 2*step)
// 128 edges/block, 256 threads, thread tile = 2 edges x 8 dims
// static smem (43.4 KB), 3 blocks/SM target
// ============================================================
#define EMLP_EB 128

__global__ __launch_bounds__(256, 3)
void edge_mlp_kernel(const float* __restrict__ edge_emb,  // [E,64]
                     const float* __restrict__ Wr1,       // [576,32]
                     const float* __restrict__ br1,       // [32]
                     const float* __restrict__ Wr2,       // [32,2]
                     const float* __restrict__ br2,       // [2]
                     const int*   __restrict__ eidx,      // [2,E]
                     int E)
{
    __shared__ float Es[EMLP_EB * 68];     // padded rows: stride 68
    __shared__ float sWe[64 * 32];
    __shared__ float sWr2[64];
    __shared__ float sb[34];

    const int tid = threadIdx.x;
    const int eb  = blockIdx.x * EMLP_EB;

    for (int i = tid; i < 2048; i += 256) sWe[i] = Wr1[i];   // We = Wr1[0:64]
    if (tid < 64) sWr2[tid] = Wr2[tid];
    if (tid < 32) sb[tid] = br1[tid];
    if (tid < 2)  sb[32 + tid] = br2[tid];

    // stage 128 edge rows (coalesced float4): 2048 float4 / 256 threads = 8 each
#pragma unroll
    for (int i = 0; i < 8; i++) {
        int gid = tid + 256 * i;
        int e = gid >> 4, q = gid & 15;
        float4 v = *reinterpret_cast<const float4*>(edge_emb + (size_t)(eb + e) * 64 + q * 4);
        *reinterpret_cast<float4*>(Es + e * 68 + q * 4) = v;
    }
    __syncthreads();

    const int eg = tid >> 2;     // 0..63 : edge group (edges eg, eg+64)
    const int dg = tid & 3;      // 0..3  : dim group (8 dims each)

    float acc[2][8];
#pragma unroll
    for (int i = 0; i < 2; i++)
#pragma unroll
        for (int j = 0; j < 8; j++) acc[i][j] = 0.f;

#pragma unroll 8
    for (int k = 0; k < 64; k++) {
        float4 b0 = *reinterpret_cast<float4*>(sWe + k * 32 + dg * 8);
        float4 b1 = *reinterpret_cast<float4*>(sWe + k * 32 + dg * 8 + 4);
        float a0 = Es[eg * 68 + k];
        float a1 = Es[(eg + 64) * 68 + k];
        acc[0][0] = fmaf(a0, b0.x, acc[0][0]);
        acc[0][1] = fmaf(a0, b0.y, acc[0][1]);
        acc[0][2] = fmaf(a0, b0.z, acc[0][2]);
        acc[0][3] = fmaf(a0, b0.w, acc[0][3]);
        acc[0][4] = fmaf(a0, b1.x, acc[0][4]);
        acc[0][5] = fmaf(a0, b1.y, acc[0][5]);
        acc[0][6] = fmaf(a0, b1.z, acc[0][6]);
        acc[0][7] = fmaf(a0, b1.w, acc[0][7]);
        acc[1][0] = fmaf(a1, b0.x, acc[1][0]);
        acc[1][1] = fmaf(a1, b0.y, acc[1][1]);
        acc[1][2] = fmaf(a1, b0.z, acc[1][2]);
        acc[1][3] = fmaf(a1, b0.w, acc[1][3]);
        acc[1][4] = fmaf(a1, b1.x, acc[1][4]);
        acc[1][5] = fmaf(a1, b1.y, acc[1][5]);
        acc[1][6] = fmaf(a1, b1.z, acc[1][6]);
        acc[1][7] = fmaf(a1, b1.w, acc[1][7]);
    }

    // epilogue: 2 edges per thread
#pragma unroll
    for (int i = 0; i < 2; i++) {
        int ge = eb + eg + 64 * i;
        int s = eidx[ge];
        int d = eidx[E + ge];
        float4 hs0 = *reinterpret_cast<const float4*>(g_hs + s * 32 + dg * 8);
        float4 hs1 = *reinterpret_cast<const float4*>(g_hs + s * 32 + dg * 8 + 4);
        float4 hd0 = *reinterpret_cast<const float4*>(g_hd + d * 32 + dg * 8);
        float4 hd1 = *reinterpret_cast<const float4*>(g_hd + d * 32 + dg * 8 + 4);
        float add[8] = {hs0.x + hd0.x, hs0.y + hd0.y, hs0.z + hd0.z, hs0.w + hd0.w,
                        hs1.x + hd1.x, hs1.y + hd1.y, hs1.z + hd1.z, hs1.w + hd1.w};
        float v0 = 0.f, v1 = 0.f;
#pragma unroll
        for (int j = 0; j < 8; j++) {
            float h = acc[i][j] + add[j] + sb[dg * 8 + j];
            h = (h >= 0.f) ? h : 0.01f * h;
            v0 = fmaf(h, sWr2[(dg * 8 + j) * 2 + 0], v0);
            v1 = fmaf(h, sWr2[(dg * 8 + j) * 2 + 1], v1);
        }
        v0 += __shfl_xor_sync(0xffffffffu, v0, 1);
        v0 += __shfl_xor_sync(0xffffffffu, v0, 2);
        v1 += __shfl_xor_sync(0xffffffffu, v1, 1);
        v1 += __shfl_xor_sync(0xffffffffu, v1, 2);
        if (dg == 0) {
            float x = v0 + sb[32] + 1.0f;
            float elen = fmaxf(x, 0.f) + log1pf(expf(-fabsf(x)));
            float y = v1 + sb[33] - 2.0f;
            float sg = 1.0f / (1.0f + expf(-y));
            g_coef[ge] = make_float2(elen, 2.0f * sg);
        }
    }
}

// ============================================================
// Refiner: one gather kernel per step (ping-pong buffers, no atomics)
// ============================================================
__global__ __launch_bounds__(256)
void refine_step_kernel(const float4* __restrict__ cin, float4* __restrict__ cout,
                        float* __restrict__ out_coords, int last, int N)
{
    int n = blockIdx.x * blockDim.x + threadIdx.x;
    if (n >= N) return;
    float4 c = cin[n];
    int p = g_ptr[n];
    int d = g_deg[n];
    float ax = 0.f, ay = 0.f, az = 0.f;
#pragma unroll 4
    for (int i = 0; i < d; i++) {
        float4 er = g_ecsr[p + i];
        int s = __float_as_int(er.z);
        float4 cs = cin[s];
        float dx = c.x - cs.x, dy = c.y - cs.y, dz = c.z - cs.z;
        float dist = sqrtf(dx * dx + dy * dy + dz * dz);
        float f = __fdividef(er.y * (er.x - dist), dist + EPSV);
        ax = fmaf(f, dx, ax);
        ay = fmaf(f, dy, ay);
        az = fmaf(f, dz, az);
    }
    float an = sqrtf(ax * ax + ay * ay + az * az) + EPSV;
    float sc = fminf(an, 0.5f) / an;
    c.x += ax * sc; c.y += ay * sc; c.z += az * sc;
    cout[n] = c;
    if (last) {
        out_coords[n * 3 + 0] = c.x;
        out_coords[n * 3 + 1] = c.y;
        out_coords[n * 3 + 2] = c.z;
    }
}

// ============================================================
// launch — two-stream fork/join (graph-capturable)
// ============================================================
extern "C" void kernel_launch(void* const* d_in, const int* in_sizes, int n_in,
                              void* d_out, int out_size)
{
    const float* node_emb  = (const float*)d_in[0];
    const float* edge_emb  = (const float*)d_in[1];
    const float* cart_init = (const float*)d_in[2];
    const float* Wt1       = (const float*)d_in[3];
    const float* bt1       = (const float*)d_in[4];
    const float* Wt2       = (const float*)d_in[5];
    const float* bt2       = (const float*)d_in[6];
    const float* Wr1       = (const float*)d_in[7];
    const float* br1       = (const float*)d_in[8];
    const float* Wr2       = (const float*)d_in[9];
    const float* br2       = (const float*)d_in[10];
    const int*   eidx      = (const int*)d_in[11];

    const int M = in_sizes[0] / NH;        // 50000
    const int E = in_sizes[1] / EH;        // 800000

    float* out = (float*)d_out;
    float* out_coords  = out;
    float* out_torsion = out + (size_t)M * 3;

    static cudaStream_t s2 = nullptr;
    static cudaEvent_t evFork = nullptr, evJoin = nullptr;
    if (!s2) {
        cudaStreamCreateWithFlags(&s2, cudaStreamNonBlocking);
        cudaEventCreateWithFlags(&evFork, cudaEventDisableTiming);
        cudaEventCreateWithFlags(&evJoin, cudaEventDisableTiming);
    }

    const int nb_nodes = (M + 255) / 256;
    const int nb_edges = (E + 255) / 256;
    const int nb_emlp  = (E + EMLP_EB - 1) / EMLP_EB;

    // fork: CSR-build chain on side stream s2
    cudaEventRecord(evFork, 0);
    cudaStreamWaitEvent(s2, evFork, 0);

    // --- call order chosen so capture index 3 = edge_mlp (profiled) ---
    init_kernel<<<nb_nodes, 256, 0, s2>>>(cart_init, M);                         // 0
    count_kernel<<<nb_edges, 256, 0, s2>>>(eidx, E);                             // 1
    node_gemm_tc<<<(M + TBM - 1) / TBM, 256>>>(node_emb, Wt1, bt1, Wt2, bt2,     // 2
                                               Wr1, out_torsion, M);
    edge_mlp_kernel<<<nb_emlp, 256>>>(edge_emb, Wr1, br1, Wr2, br2, eidx, E);    // 3
    scan1_kernel<<<nb_nodes, 256, 0, s2>>>(M);                                   // 4
    scan2_kernel<<<1, 256, 0, s2>>>(nb_nodes);                                   // 5
    scan3_kernel<<<nb_nodes, 256, 0, s2>>>(M);                                   // 6

    // join: fill needs cursor (s2) + coef (stream 0)
    cudaEventRecord(evJoin, s2);
    cudaStreamWaitEvent(0, evJoin, 0);

    fill_kernel<<<nb_edges, 256>>>(eidx, E);                                     // 7

    float4* bufs[2];
    cudaGetSymbolAddress((void**)&bufs[0], g_cA);
    cudaGetSymbolAddress((void**)&bufs[1], g_cB);
    for (int s = 0; s < NSTEPS; s++) {
        refine_step_kernel<<<nb_nodes, 256>>>(bufs[s & 1], bufs[(s + 1) & 1],
                                              out_coords, (s == NSTEPS - 1) ? 1 : 0, M);
    }
}